// round 4
// baseline (speedup 1.0000x reference)
#include <cuda_runtime.h>
#include <cuda_bf16.h>
#include <math.h>
#include <stdint.h>

#define E_DIM 768
#define H_NUM 12
#define D_DIM 64
#define B_NUM 4
#define S_LEN 2048
#define M_ROWS (B_NUM * S_LEN)   // 8192

// Scratch (static device globals: allocation-free)
__device__ float g_Qh[B_NUM * H_NUM * S_LEN * D_DIM];   // [B,H,S,D]
__device__ float g_Kh[B_NUM * H_NUM * S_LEN * D_DIM];
__device__ float g_Vh[B_NUM * H_NUM * S_LEN * D_DIM];
__device__ float g_ctx[M_ROWS * E_DIM];                 // [B,S,E]

// ---------------------------------------------------------------------------
// helpers
// ---------------------------------------------------------------------------
__device__ __forceinline__ uint32_t f2tf32(float x) {
    uint32_t u;
    asm("cvt.rna.tf32.f32 %0, %1;" : "=r"(u) : "f"(x));
    return u;
}

__device__ __forceinline__ void mma_tf32(float* d, const uint32_t* a,
                                         uint32_t b0, uint32_t b1) {
    asm volatile(
        "mma.sync.aligned.m16n8k8.row.col.f32.tf32.tf32.f32 "
        "{%0,%1,%2,%3}, {%4,%5,%6,%7}, {%8,%9}, {%0,%1,%2,%3};\n"
        : "+f"(d[0]), "+f"(d[1]), "+f"(d[2]), "+f"(d[3])
        : "r"(a[0]), "r"(a[1]), "r"(a[2]), "r"(a[3]), "r"(b0), "r"(b1));
}

__device__ __forceinline__ float ex2(float x) {
    float y;
    asm("ex2.approx.ftz.f32 %0, %1;" : "=f"(y) : "f"(x));
    return y;
}

__device__ __forceinline__ void cp16(uint32_t dst_smem, const void* src) {
    asm volatile("cp.async.ca.shared.global [%0], [%1], 16;\n"
                 :: "r"(dst_smem), "l"(src));
}
#define CP_COMMIT() asm volatile("cp.async.commit_group;\n")
#define CP_WAIT1()  asm volatile("cp.async.wait_group 1;\n")
#define CP_WAIT0()  asm volatile("cp.async.wait_group 0;\n")

// ---------------------------------------------------------------------------
// Tensor-core GEMM, cp.async double-buffered.
// Block tile 128x64, BK=32, 256 threads (8 warps, 4x2 warp grid, 32x32/warp).
// Merged QKV launch: blockIdx.z selects (X, W, bias, out).
// HEADS_OUT: scatter into [B,H,S,D] layout (head = blockIdx.x).
// ---------------------------------------------------------------------------
#define AS_WORDS (128 * 36)
#define BS_WORDS (32 * 72)
#define STAGE_WORDS (AS_WORDS + BS_WORDS)

__device__ __forceinline__ void gemm_issue(uint32_t as_b, uint32_t bs_b,
                                           const float* __restrict__ X,
                                           const float* __restrict__ W,
                                           int m0, int n0, int k0, int tid) {
    const int r = tid >> 3, c4 = (tid & 7) * 4;
#pragma unroll
    for (int i = 0; i < 4; i++)
        cp16(as_b + (uint32_t)(((r + i * 32) * 36 + c4) * 4),
             X + (long)(m0 + r + i * 32) * E_DIM + k0 + c4);
    const int r2 = tid >> 4, cc = (tid & 15) * 4;
#pragma unroll
    for (int i = 0; i < 2; i++)
        cp16(bs_b + (uint32_t)(((r2 + i * 16) * 72 + cc) * 4),
             W + (long)(k0 + r2 + i * 16) * E_DIM + n0 + cc);
}

template <bool HEADS_OUT>
__global__ __launch_bounds__(256) void gemm_tc(
    const float* __restrict__ X0, const float* __restrict__ X1,
    const float* __restrict__ X2,
    const float* __restrict__ W0, const float* __restrict__ W1,
    const float* __restrict__ W2,
    const float* __restrict__ bias0, const float* __restrict__ bias1,
    const float* __restrict__ bias2,
    float* __restrict__ out0, float* __restrict__ out1,
    float* __restrict__ out2) {
    extern __shared__ float smg[];

    const int z = blockIdx.z;
    const float* X = (z == 0) ? X0 : (z == 1) ? X1 : X2;
    const float* W = (z == 0) ? W0 : (z == 1) ? W1 : W2;
    const float* bias = (z == 0) ? bias0 : (z == 1) ? bias1 : bias2;
    float* out = (z == 0) ? out0 : (z == 1) ? out1 : out2;

    const int tid = threadIdx.x;
    const int w = tid >> 5, lane = tid & 31;
    const int wm = w >> 1, wn = w & 1;
    const int g = lane >> 2, c = lane & 3;
    const int m0 = blockIdx.y * 128, n0 = blockIdx.x * 64;

    const uint32_t sbase = (uint32_t)__cvta_generic_to_shared(smg);

    float acc[2][4][4];
#pragma unroll
    for (int mt = 0; mt < 2; mt++)
#pragma unroll
        for (int nt = 0; nt < 4; nt++)
#pragma unroll
            for (int j = 0; j < 4; j++) acc[mt][nt][j] = 0.0f;

    // prologue: stage 0
    gemm_issue(sbase, sbase + AS_WORDS * 4, X, W, m0, n0, 0, tid);
    CP_COMMIT();

    const int NT = E_DIM / 32;  // 24
    for (int t = 0; t < NT; t++) {
        if (t < NT - 1) {
            const uint32_t sb = sbase + (uint32_t)(((t + 1) & 1) * STAGE_WORDS * 4);
            gemm_issue(sb, sb + AS_WORDS * 4, X, W, m0, n0, (t + 1) * 32, tid);
            CP_COMMIT();
            CP_WAIT1();
        } else {
            CP_WAIT0();
        }
        __syncthreads();

        const float* As = smg + (t & 1) * STAGE_WORDS;
        const float* Bs = As + AS_WORDS;

#pragma unroll
        for (int ks = 0; ks < 4; ks++) {
            uint32_t a[2][4];
#pragma unroll
            for (int mt = 0; mt < 2; mt++) {
                const float* ap = &As[(wm * 32 + mt * 16 + g) * 36 + ks * 8 + c];
                a[mt][0] = f2tf32(ap[0]);
                a[mt][1] = f2tf32(ap[8 * 36]);
                a[mt][2] = f2tf32(ap[4]);
                a[mt][3] = f2tf32(ap[8 * 36 + 4]);
            }
#pragma unroll
            for (int nt = 0; nt < 4; nt++) {
                const uint32_t b0 =
                    f2tf32(Bs[(ks * 8 + c) * 72 + wn * 32 + nt * 8 + g]);
                const uint32_t b1 =
                    f2tf32(Bs[(ks * 8 + c + 4) * 72 + wn * 32 + nt * 8 + g]);
                mma_tf32(acc[0][nt], a[0], b0, b1);
                mma_tf32(acc[1][nt], a[1], b0, b1);
            }
        }
        __syncthreads();
    }

    // Epilogue
#pragma unroll
    for (int mt = 0; mt < 2; mt++) {
        const int r0 = m0 + wm * 32 + mt * 16 + g;
#pragma unroll
        for (int nt = 0; nt < 4; nt++) {
            const int col = n0 + wn * 32 + nt * 8 + 2 * c;
            const float bb0 = bias[col], bb1 = bias[col + 1];
            const float v00 = acc[mt][nt][0] + bb0;
            const float v01 = acc[mt][nt][1] + bb1;
            const float v10 = acc[mt][nt][2] + bb0;
            const float v11 = acc[mt][nt][3] + bb1;
            if (HEADS_OUT) {
                const int d = col & 63;
                const int b0i = r0 >> 11, s0 = r0 & 2047;
                const int r1 = r0 + 8;
                const int b1i = r1 >> 11, s1 = r1 & 2047;
                *(float2*)&out[((long)(b0i * H_NUM + blockIdx.x) * S_LEN + s0) * D_DIM + d] =
                    make_float2(v00, v01);
                *(float2*)&out[((long)(b1i * H_NUM + blockIdx.x) * S_LEN + s1) * D_DIM + d] =
                    make_float2(v10, v11);
            } else {
                *(float2*)&out[(long)r0 * E_DIM + col] = make_float2(v00, v01);
                *(float2*)&out[(long)(r0 + 8) * E_DIM + col] = make_float2(v10, v11);
            }
        }
    }
}

// ---------------------------------------------------------------------------
// Tensor-core flash attention. Block = 4 warps, Br=64, Bc=64, D=64.
// K,V stored as tf32 (converted once at load, stride 72 -> conflict-free).
// P never touches smem: PV A-fragments built from S C-fragments via shuffles.
// ---------------------------------------------------------------------------
#define SCALE2 (0.125f * 1.44269504088896f)  // 1/sqrt(64) * log2(e)

__global__ __launch_bounds__(128) void attn_tc(const int* __restrict__ mask,
                                               const float* __restrict__ Qh,
                                               const float* __restrict__ Kh,
                                               const float* __restrict__ Vh,
                                               float* __restrict__ ctx) {
    __shared__ uint32_t Ks[64 * 72];
    __shared__ uint32_t Vs[64 * 72];
    __shared__ float biasS[64];

    const int b = blockIdx.z, h = blockIdx.y;
    const int q0 = blockIdx.x * 64;
    const int tid = threadIdx.x;
    const int lane = tid & 31, w = tid >> 5;
    const int g = lane >> 2, c = lane & 3;

    const long base = (long)(b * H_NUM + h) * S_LEN * D_DIM;
    const float* Q = Qh + base;
    const float* K = Kh + base;
    const float* V = Vh + base;

    // Q fragments (pre-scaled tf32), held in registers for the whole kernel
    uint32_t aq[8][4];
    {
        const float* q_r0 = Q + (long)(q0 + w * 16 + g) * D_DIM;
        const float* q_r1 = q_r0 + 8 * D_DIM;
#pragma unroll
        for (int ks = 0; ks < 8; ks++) {
            aq[ks][0] = f2tf32(q_r0[ks * 8 + c] * SCALE2);
            aq[ks][1] = f2tf32(q_r1[ks * 8 + c] * SCALE2);
            aq[ks][2] = f2tf32(q_r0[ks * 8 + c + 4] * SCALE2);
            aq[ks][3] = f2tf32(q_r1[ks * 8 + c + 4] * SCALE2);
        }
    }

    float O[8][4];
#pragma unroll
    for (int nt = 0; nt < 8; nt++)
#pragma unroll
        for (int j = 0; j < 4; j++) O[nt][j] = 0.0f;
    float mm0 = -1e30f, mm1 = -1e30f, l0 = 0.0f, l1 = 0.0f;

    const int r_ld = tid >> 1;        // 0..63 : row this thread loads
    const int f_par = tid & 1;        // float4-column parity
    const int srcA = (lane & 28) | (c >> 1);
    const int srcB = srcA + 2;
    const bool codd = (c & 1);

    for (int k0 = 0; k0 < S_LEN; k0 += 64) {
        __syncthreads();  // all reads of previous tile finished
        // load + convert K,V tiles to tf32
#pragma unroll
        for (int i = 0; i < 8; i++) {
            const int col = (f_par + 2 * i) * 4;
            float4 kv = *(const float4*)&K[(long)(k0 + r_ld) * D_DIM + col];
            float4 vv = *(const float4*)&V[(long)(k0 + r_ld) * D_DIM + col];
            uint4 ku = make_uint4(f2tf32(kv.x), f2tf32(kv.y), f2tf32(kv.z), f2tf32(kv.w));
            uint4 vu = make_uint4(f2tf32(vv.x), f2tf32(vv.y), f2tf32(vv.z), f2tf32(vv.w));
            *(uint4*)&Ks[r_ld * 72 + col] = ku;
            *(uint4*)&Vs[r_ld * 72 + col] = vu;
        }
        if (tid < 64)
            biasS[tid] = mask[b * S_LEN + k0 + tid] ? 0.0f : -1.442695e9f;
        __syncthreads();

        // S = (Q*scale) K^T  (base-2 domain)
        float S[8][4];
#pragma unroll
        for (int nt = 0; nt < 8; nt++)
#pragma unroll
            for (int j = 0; j < 4; j++) S[nt][j] = 0.0f;

#pragma unroll
        for (int ks = 0; ks < 8; ks++) {
#pragma unroll
            for (int nt = 0; nt < 8; nt++) {
                const uint32_t b0 = Ks[(nt * 8 + g) * 72 + ks * 8 + c];
                const uint32_t b1 = Ks[(nt * 8 + g) * 72 + ks * 8 + c + 4];
                mma_tf32(S[nt], aq[ks], b0, b1);
            }
        }

        // mask bias + online softmax
        float mx0 = -1e30f, mx1 = -1e30f;
#pragma unroll
        for (int nt = 0; nt < 8; nt++) {
            const float bb0 = biasS[nt * 8 + 2 * c];
            const float bb1 = biasS[nt * 8 + 2 * c + 1];
            S[nt][0] += bb0;
            S[nt][1] += bb1;
            S[nt][2] += bb0;
            S[nt][3] += bb1;
            mx0 = fmaxf(mx0, fmaxf(S[nt][0], S[nt][1]));
            mx1 = fmaxf(mx1, fmaxf(S[nt][2], S[nt][3]));
        }
        mx0 = fmaxf(mx0, __shfl_xor_sync(0xffffffffu, mx0, 1));
        mx0 = fmaxf(mx0, __shfl_xor_sync(0xffffffffu, mx0, 2));
        mx1 = fmaxf(mx1, __shfl_xor_sync(0xffffffffu, mx1, 1));
        mx1 = fmaxf(mx1, __shfl_xor_sync(0xffffffffu, mx1, 2));

        const float M0 = fmaxf(mm0, mx0), M1 = fmaxf(mm1, mx1);
        const float a0 = ex2(mm0 - M0), a1 = ex2(mm1 - M1);
        mm0 = M0;
        mm1 = M1;

        float s0 = 0.0f, s1 = 0.0f;
#pragma unroll
        for (int nt = 0; nt < 8; nt++) {
            S[nt][0] = ex2(S[nt][0] - M0);
            S[nt][1] = ex2(S[nt][1] - M0);
            S[nt][2] = ex2(S[nt][2] - M1);
            S[nt][3] = ex2(S[nt][3] - M1);
            s0 += S[nt][0] + S[nt][1];
            s1 += S[nt][2] + S[nt][3];
        }
        s0 += __shfl_xor_sync(0xffffffffu, s0, 1);
        s0 += __shfl_xor_sync(0xffffffffu, s0, 2);
        s1 += __shfl_xor_sync(0xffffffffu, s1, 1);
        s1 += __shfl_xor_sync(0xffffffffu, s1, 2);
        l0 = l0 * a0 + s0;
        l1 = l1 * a1 + s1;

#pragma unroll
        for (int nt = 0; nt < 8; nt++) {
            O[nt][0] *= a0;
            O[nt][1] *= a0;
            O[nt][2] *= a1;
            O[nt][3] *= a1;
        }

        // convert P fragments to tf32 in registers
        uint32_t Su[8][4];
#pragma unroll
        for (int nt = 0; nt < 8; nt++)
#pragma unroll
            for (int j = 0; j < 4; j++) Su[nt][j] = f2tf32(S[nt][j]);

        // O += P @ V ; A-fragments via intra-quad shuffles (C->A layout fix)
#pragma unroll
        for (int ks = 0; ks < 8; ks++) {
            uint32_t ap[4];
            {
                uint32_t t0 = __shfl_sync(0xffffffffu, Su[ks][0], srcA);
                uint32_t t1 = __shfl_sync(0xffffffffu, Su[ks][1], srcA);
                ap[0] = codd ? t1 : t0;
                uint32_t t2 = __shfl_sync(0xffffffffu, Su[ks][2], srcA);
                uint32_t t3 = __shfl_sync(0xffffffffu, Su[ks][3], srcA);
                ap[1] = codd ? t3 : t2;
                uint32_t u0 = __shfl_sync(0xffffffffu, Su[ks][0], srcB);
                uint32_t u1 = __shfl_sync(0xffffffffu, Su[ks][1], srcB);
                ap[2] = codd ? u1 : u0;
                uint32_t u2 = __shfl_sync(0xffffffffu, Su[ks][2], srcB);
                uint32_t u3 = __shfl_sync(0xffffffffu, Su[ks][3], srcB);
                ap[3] = codd ? u3 : u2;
            }
#pragma unroll
            for (int nt = 0; nt < 8; nt++) {
                const uint32_t b0 = Vs[(ks * 8 + c) * 72 + nt * 8 + g];
                const uint32_t b1 = Vs[(ks * 8 + c + 4) * 72 + nt * 8 + g];
                mma_tf32(O[nt], ap, b0, b1);
            }
        }
    }

    // epilogue: ctx[b][row][h*64 + col] = O / l
    const float inv0 = 1.0f / l0, inv1 = 1.0f / l1;
    const int r0 = q0 + w * 16 + g;
#pragma unroll
    for (int nt = 0; nt < 8; nt++) {
        const int col = h * D_DIM + nt * 8 + 2 * c;
        *(float2*)&ctx[((long)b * S_LEN + r0) * E_DIM + col] =
            make_float2(O[nt][0] * inv0, O[nt][1] * inv0);
        *(float2*)&ctx[((long)b * S_LEN + r0 + 8) * E_DIM + col] =
            make_float2(O[nt][2] * inv1, O[nt][3] * inv1);
    }
}

// ---------------------------------------------------------------------------
extern "C" void kernel_launch(void* const* d_in, const int* in_sizes, int n_in,
                              void* d_out, int out_size) {
    const float* q = (const float*)d_in[0];
    const float* k = (const float*)d_in[1];
    const float* v = (const float*)d_in[2];
    const int* mask = (const int*)d_in[3];
    const float* Wq = (const float*)d_in[4];
    const float* bq = (const float*)d_in[5];
    const float* Wk = (const float*)d_in[6];
    const float* bk = (const float*)d_in[7];
    const float* Wv = (const float*)d_in[8];
    const float* bv = (const float*)d_in[9];
    const float* Wo = (const float*)d_in[10];
    const float* bo = (const float*)d_in[11];

    float *Qh, *Kh, *Vh, *Ctx;
    cudaGetSymbolAddress((void**)&Qh, g_Qh);
    cudaGetSymbolAddress((void**)&Kh, g_Kh);
    cudaGetSymbolAddress((void**)&Vh, g_Vh);
    cudaGetSymbolAddress((void**)&Ctx, g_ctx);

    const int gemm_smem = STAGE_WORDS * 2 * sizeof(float);  // 55296 B
    cudaFuncSetAttribute(gemm_tc<true>, cudaFuncAttributeMaxDynamicSharedMemorySize, gemm_smem);
    cudaFuncSetAttribute(gemm_tc<false>, cudaFuncAttributeMaxDynamicSharedMemorySize, gemm_smem);

    // merged Q/K/V projections
    gemm_tc<true><<<dim3(E_DIM / 64, M_ROWS / 128, 3), 256, gemm_smem>>>(
        q, k, v, Wq, Wk, Wv, bq, bk, bv, Qh, Kh, Vh);

    attn_tc<<<dim3(S_LEN / 64, H_NUM, B_NUM), 128>>>(mask, Qh, Kh, Vh, Ctx);

    gemm_tc<false><<<dim3(E_DIM / 64, M_ROWS / 128, 1), 256, gemm_smem>>>(
        Ctx, Ctx, Ctx, Wo, Wo, Wo, bo, bo, bo, (float*)d_out, (float*)d_out,
        (float*)d_out);
}

// round 5
// speedup vs baseline: 1.3409x; 1.3409x over previous
#include <cuda_runtime.h>
#include <cuda_bf16.h>
#include <cuda_fp16.h>
#include <math.h>
#include <stdint.h>

#define E_DIM 768
#define H_NUM 12
#define D_DIM 64
#define B_NUM 4
#define S_LEN 2048
#define M_ROWS (B_NUM * S_LEN)   // 8192

// Scratch (static device globals: allocation-free)
__device__ float g_Qh[B_NUM * H_NUM * S_LEN * D_DIM];   // [B,H,S,D]
__device__ float g_Kh[B_NUM * H_NUM * S_LEN * D_DIM];
__device__ float g_Vh[B_NUM * H_NUM * S_LEN * D_DIM];
__device__ float g_ctx[M_ROWS * E_DIM];                 // [B,S,E]

// ---------------------------------------------------------------------------
// helpers
// ---------------------------------------------------------------------------
__device__ __forceinline__ uint32_t f2tf32(float x) {
    uint32_t u;
    asm("cvt.rna.tf32.f32 %0, %1;" : "=r"(u) : "f"(x));
    return u;
}

__device__ __forceinline__ void mma_tf32(float* d, const uint32_t* a,
                                         uint32_t b0, uint32_t b1) {
    asm volatile(
        "mma.sync.aligned.m16n8k8.row.col.f32.tf32.tf32.f32 "
        "{%0,%1,%2,%3}, {%4,%5,%6,%7}, {%8,%9}, {%0,%1,%2,%3};\n"
        : "+f"(d[0]), "+f"(d[1]), "+f"(d[2]), "+f"(d[3])
        : "r"(a[0]), "r"(a[1]), "r"(a[2]), "r"(a[3]), "r"(b0), "r"(b1));
}

__device__ __forceinline__ void mma_f16(float* d, uint32_t a0, uint32_t a1,
                                        uint32_t a2, uint32_t a3, uint32_t b0,
                                        uint32_t b1) {
    asm volatile(
        "mma.sync.aligned.m16n8k16.row.col.f32.f16.f16.f32 "
        "{%0,%1,%2,%3}, {%4,%5,%6,%7}, {%8,%9}, {%0,%1,%2,%3};\n"
        : "+f"(d[0]), "+f"(d[1]), "+f"(d[2]), "+f"(d[3])
        : "r"(a0), "r"(a1), "r"(a2), "r"(a3), "r"(b0), "r"(b1));
}

__device__ __forceinline__ float ex2(float x) {
    float y;
    asm("ex2.approx.ftz.f32 %0, %1;" : "=f"(y) : "f"(x));
    return y;
}

__device__ __forceinline__ uint32_t pack_h2(float lo, float hi) {
    __half2 h = __floats2half2_rn(lo, hi);
    return *(uint32_t*)&h;
}

__device__ __forceinline__ void cp16(uint32_t dst_smem, const void* src) {
    asm volatile("cp.async.ca.shared.global [%0], [%1], 16;\n"
                 :: "r"(dst_smem), "l"(src));
}
#define CP_COMMIT() asm volatile("cp.async.commit_group;\n")
#define CP_WAIT1()  asm volatile("cp.async.wait_group 1;\n")
#define CP_WAIT0()  asm volatile("cp.async.wait_group 0;\n")

// ---------------------------------------------------------------------------
// Tensor-core GEMM, cp.async double-buffered (identical to R4 measured-good).
// ---------------------------------------------------------------------------
#define AS_WORDS (128 * 36)
#define BS_WORDS (32 * 72)
#define STAGE_WORDS (AS_WORDS + BS_WORDS)

__device__ __forceinline__ void gemm_issue(uint32_t as_b, uint32_t bs_b,
                                           const float* __restrict__ X,
                                           const float* __restrict__ W,
                                           int m0, int n0, int k0, int tid) {
    const int r = tid >> 3, c4 = (tid & 7) * 4;
#pragma unroll
    for (int i = 0; i < 4; i++)
        cp16(as_b + (uint32_t)(((r + i * 32) * 36 + c4) * 4),
             X + (long)(m0 + r + i * 32) * E_DIM + k0 + c4);
    const int r2 = tid >> 4, cc = (tid & 15) * 4;
#pragma unroll
    for (int i = 0; i < 2; i++)
        cp16(bs_b + (uint32_t)(((r2 + i * 16) * 72 + cc) * 4),
             W + (long)(k0 + r2 + i * 16) * E_DIM + n0 + cc);
}

template <bool HEADS_OUT>
__global__ __launch_bounds__(256) void gemm_tc(
    const float* __restrict__ X0, const float* __restrict__ X1,
    const float* __restrict__ X2,
    const float* __restrict__ W0, const float* __restrict__ W1,
    const float* __restrict__ W2,
    const float* __restrict__ bias0, const float* __restrict__ bias1,
    const float* __restrict__ bias2,
    float* __restrict__ out0, float* __restrict__ out1,
    float* __restrict__ out2) {
    extern __shared__ float smg[];

    const int z = blockIdx.z;
    const float* X = (z == 0) ? X0 : (z == 1) ? X1 : X2;
    const float* W = (z == 0) ? W0 : (z == 1) ? W1 : W2;
    const float* bias = (z == 0) ? bias0 : (z == 1) ? bias1 : bias2;
    float* out = (z == 0) ? out0 : (z == 1) ? out1 : out2;

    const int tid = threadIdx.x;
    const int w = tid >> 5, lane = tid & 31;
    const int wm = w >> 1, wn = w & 1;
    const int g = lane >> 2, c = lane & 3;
    const int m0 = blockIdx.y * 128, n0 = blockIdx.x * 64;

    const uint32_t sbase = (uint32_t)__cvta_generic_to_shared(smg);

    float acc[2][4][4];
#pragma unroll
    for (int mt = 0; mt < 2; mt++)
#pragma unroll
        for (int nt = 0; nt < 4; nt++)
#pragma unroll
            for (int j = 0; j < 4; j++) acc[mt][nt][j] = 0.0f;

    gemm_issue(sbase, sbase + AS_WORDS * 4, X, W, m0, n0, 0, tid);
    CP_COMMIT();

    const int NT = E_DIM / 32;  // 24
    for (int t = 0; t < NT; t++) {
        if (t < NT - 1) {
            const uint32_t sb = sbase + (uint32_t)(((t + 1) & 1) * STAGE_WORDS * 4);
            gemm_issue(sb, sb + AS_WORDS * 4, X, W, m0, n0, (t + 1) * 32, tid);
            CP_COMMIT();
            CP_WAIT1();
        } else {
            CP_WAIT0();
        }
        __syncthreads();

        const float* As = smg + (t & 1) * STAGE_WORDS;
        const float* Bs = As + AS_WORDS;

#pragma unroll
        for (int ks = 0; ks < 4; ks++) {
            uint32_t a[2][4];
#pragma unroll
            for (int mt = 0; mt < 2; mt++) {
                const float* ap = &As[(wm * 32 + mt * 16 + g) * 36 + ks * 8 + c];
                a[mt][0] = f2tf32(ap[0]);
                a[mt][1] = f2tf32(ap[8 * 36]);
                a[mt][2] = f2tf32(ap[4]);
                a[mt][3] = f2tf32(ap[8 * 36 + 4]);
            }
#pragma unroll
            for (int nt = 0; nt < 4; nt++) {
                const uint32_t b0 =
                    f2tf32(Bs[(ks * 8 + c) * 72 + wn * 32 + nt * 8 + g]);
                const uint32_t b1 =
                    f2tf32(Bs[(ks * 8 + c + 4) * 72 + wn * 32 + nt * 8 + g]);
                mma_tf32(acc[0][nt], a[0], b0, b1);
                mma_tf32(acc[1][nt], a[1], b0, b1);
            }
        }
        __syncthreads();
    }

#pragma unroll
    for (int mt = 0; mt < 2; mt++) {
        const int r0 = m0 + wm * 32 + mt * 16 + g;
#pragma unroll
        for (int nt = 0; nt < 4; nt++) {
            const int col = n0 + wn * 32 + nt * 8 + 2 * c;
            const float bb0 = bias[col], bb1 = bias[col + 1];
            const float v00 = acc[mt][nt][0] + bb0;
            const float v01 = acc[mt][nt][1] + bb1;
            const float v10 = acc[mt][nt][2] + bb0;
            const float v11 = acc[mt][nt][3] + bb1;
            if (HEADS_OUT) {
                const int d = col & 63;
                const int b0i = r0 >> 11, s0 = r0 & 2047;
                const int r1 = r0 + 8;
                const int b1i = r1 >> 11, s1 = r1 & 2047;
                *(float2*)&out[((long)(b0i * H_NUM + blockIdx.x) * S_LEN + s0) * D_DIM + d] =
                    make_float2(v00, v01);
                *(float2*)&out[((long)(b1i * H_NUM + blockIdx.x) * S_LEN + s1) * D_DIM + d] =
                    make_float2(v10, v11);
            } else {
                *(float2*)&out[(long)r0 * E_DIM + col] = make_float2(v00, v01);
                *(float2*)&out[(long)(r0 + 8) * E_DIM + col] = make_float2(v10, v11);
            }
        }
    }
}

// ---------------------------------------------------------------------------
// fp16 tensor-core flash attention. Block = 4 warps, Br=64, Bc=64, D=64.
// m16n8k16 f16 mma, f32 accum. K stored [key][d] as half (stride 72),
// V stored TRANSPOSED [d][key] as half (stride 72). P stays in registers:
// QK C-fragments pack directly into PV A-fragments (FA2 layout trick).
// ---------------------------------------------------------------------------
#define SCALE2 (0.125f * 1.44269504088896f)  // 1/sqrt(64) * log2(e)
#define KSTRIDE 72

__global__ __launch_bounds__(128) void attn_f16(const int* __restrict__ mask,
                                                const float* __restrict__ Qh,
                                                const float* __restrict__ Kh,
                                                const float* __restrict__ Vh,
                                                float* __restrict__ ctx) {
    __shared__ __half Ks[64 * KSTRIDE];    // [key][d]
    __shared__ __half VsT[64 * KSTRIDE];   // [d][key]
    __shared__ float biasS[64];

    const int b = blockIdx.z, h = blockIdx.y;
    const int q0 = blockIdx.x * 64;
    const int tid = threadIdx.x;
    const int lane = tid & 31, w = tid >> 5;
    const int g = lane >> 2, c = lane & 3;

    const long base = (long)(b * H_NUM + h) * S_LEN * D_DIM;
    const float* Q = Qh + base;
    const float* K = Kh + base;
    const float* V = Vh + base;

    // Q A-fragments (pre-scaled, fp16-packed): aq[ks][0]=row g cols 2c..,
    // [1]=row g+8, [2]=row g cols 2c+8.., [3]=row g+8 cols 2c+8..
    uint32_t aq[4][4];
    {
        const float* q_r0 = Q + (long)(q0 + w * 16 + g) * D_DIM;
        const float* q_r1 = q_r0 + 8 * D_DIM;
#pragma unroll
        for (int ks = 0; ks < 4; ks++) {
            float2 p0 = *(const float2*)&q_r0[ks * 16 + 2 * c];
            float2 p1 = *(const float2*)&q_r1[ks * 16 + 2 * c];
            float2 p2 = *(const float2*)&q_r0[ks * 16 + 2 * c + 8];
            float2 p3 = *(const float2*)&q_r1[ks * 16 + 2 * c + 8];
            aq[ks][0] = pack_h2(p0.x * SCALE2, p0.y * SCALE2);
            aq[ks][1] = pack_h2(p1.x * SCALE2, p1.y * SCALE2);
            aq[ks][2] = pack_h2(p2.x * SCALE2, p2.y * SCALE2);
            aq[ks][3] = pack_h2(p3.x * SCALE2, p3.y * SCALE2);
        }
    }

    float O[8][4];
#pragma unroll
    for (int nt = 0; nt < 8; nt++)
#pragma unroll
        for (int j = 0; j < 4; j++) O[nt][j] = 0.0f;
    float mm0 = -1e30f, mm1 = -1e30f, l0 = 0.0f, l1 = 0.0f;

    const int r_ld = tid >> 1;        // 0..63 : key row this thread loads
    const int f_par = tid & 1;

    for (int k0 = 0; k0 < S_LEN; k0 += 64) {
        __syncthreads();  // all reads of previous tile finished
        // load K -> Ks [key][d], V -> VsT [d][key] (fp16 convert once)
#pragma unroll
        for (int i = 0; i < 8; i++) {
            const int col = (f_par + 2 * i) * 4;
            float4 kv = *(const float4*)&K[(long)(k0 + r_ld) * D_DIM + col];
            float4 vv = *(const float4*)&V[(long)(k0 + r_ld) * D_DIM + col];
            *(uint32_t*)&Ks[r_ld * KSTRIDE + col] = pack_h2(kv.x, kv.y);
            *(uint32_t*)&Ks[r_ld * KSTRIDE + col + 2] = pack_h2(kv.z, kv.w);
            VsT[(col + 0) * KSTRIDE + r_ld] = __float2half(vv.x);
            VsT[(col + 1) * KSTRIDE + r_ld] = __float2half(vv.y);
            VsT[(col + 2) * KSTRIDE + r_ld] = __float2half(vv.z);
            VsT[(col + 3) * KSTRIDE + r_ld] = __float2half(vv.w);
        }
        if (tid < 64)
            biasS[tid] = mask[b * S_LEN + k0 + tid] ? 0.0f : -1.442695e9f;
        __syncthreads();

        // S = (Q*scale) K^T  (base-2 domain)
        float S[8][4];
#pragma unroll
        for (int nt = 0; nt < 8; nt++)
#pragma unroll
            for (int j = 0; j < 4; j++) S[nt][j] = 0.0f;

#pragma unroll
        for (int ks = 0; ks < 4; ks++) {
#pragma unroll
            for (int nt = 0; nt < 8; nt++) {
                const uint32_t b0 =
                    *(const uint32_t*)&Ks[(nt * 8 + g) * KSTRIDE + ks * 16 + 2 * c];
                const uint32_t b1 =
                    *(const uint32_t*)&Ks[(nt * 8 + g) * KSTRIDE + ks * 16 + 2 * c + 8];
                mma_f16(S[nt], aq[ks][0], aq[ks][1], aq[ks][2], aq[ks][3], b0, b1);
            }
        }

        // mask bias + online softmax (rows r0 = w*16+g, r1 = r0+8)
        float mx0 = -1e30f, mx1 = -1e30f;
#pragma unroll
        for (int nt = 0; nt < 8; nt++) {
            const float bb0 = biasS[nt * 8 + 2 * c];
            const float bb1 = biasS[nt * 8 + 2 * c + 1];
            S[nt][0] += bb0;
            S[nt][1] += bb1;
            S[nt][2] += bb0;
            S[nt][3] += bb1;
            mx0 = fmaxf(mx0, fmaxf(S[nt][0], S[nt][1]));
            mx1 = fmaxf(mx1, fmaxf(S[nt][2], S[nt][3]));
        }
        mx0 = fmaxf(mx0, __shfl_xor_sync(0xffffffffu, mx0, 1));
        mx0 = fmaxf(mx0, __shfl_xor_sync(0xffffffffu, mx0, 2));
        mx1 = fmaxf(mx1, __shfl_xor_sync(0xffffffffu, mx1, 1));
        mx1 = fmaxf(mx1, __shfl_xor_sync(0xffffffffu, mx1, 2));

        const float M0 = fmaxf(mm0, mx0), M1 = fmaxf(mm1, mx1);
        const float a0 = ex2(mm0 - M0), a1 = ex2(mm1 - M1);
        mm0 = M0;
        mm1 = M1;

        float s0 = 0.0f, s1 = 0.0f;
        uint32_t Pp[8][2];  // packed P: [nt][0]=row g half2, [1]=row g+8 half2
#pragma unroll
        for (int nt = 0; nt < 8; nt++) {
            S[nt][0] = ex2(S[nt][0] - M0);
            S[nt][1] = ex2(S[nt][1] - M0);
            S[nt][2] = ex2(S[nt][2] - M1);
            S[nt][3] = ex2(S[nt][3] - M1);
            s0 += S[nt][0] + S[nt][1];
            s1 += S[nt][2] + S[nt][3];
            Pp[nt][0] = pack_h2(S[nt][0], S[nt][1]);
            Pp[nt][1] = pack_h2(S[nt][2], S[nt][3]);
        }
        s0 += __shfl_xor_sync(0xffffffffu, s0, 1);
        s0 += __shfl_xor_sync(0xffffffffu, s0, 2);
        s1 += __shfl_xor_sync(0xffffffffu, s1, 1);
        s1 += __shfl_xor_sync(0xffffffffu, s1, 2);
        l0 = l0 * a0 + s0;
        l1 = l1 * a1 + s1;

#pragma unroll
        for (int nt = 0; nt < 8; nt++) {
            O[nt][0] *= a0;
            O[nt][1] *= a0;
            O[nt][2] *= a1;
            O[nt][3] *= a1;
        }

        // O += P @ V : A-frags are (Pp[2ks], Pp[2ks+1]) — layout-exact, no shuffles
#pragma unroll
        for (int ks = 0; ks < 4; ks++) {
#pragma unroll
            for (int nt = 0; nt < 8; nt++) {
                const uint32_t b0 =
                    *(const uint32_t*)&VsT[(nt * 8 + g) * KSTRIDE + ks * 16 + 2 * c];
                const uint32_t b1 =
                    *(const uint32_t*)&VsT[(nt * 8 + g) * KSTRIDE + ks * 16 + 2 * c + 8];
                mma_f16(O[nt], Pp[2 * ks][0], Pp[2 * ks][1], Pp[2 * ks + 1][0],
                        Pp[2 * ks + 1][1], b0, b1);
            }
        }
    }

    // epilogue: ctx[b][row][h*64 + col] = O / l
    const float inv0 = 1.0f / l0, inv1 = 1.0f / l1;
    const int r0 = q0 + w * 16 + g;
#pragma unroll
    for (int nt = 0; nt < 8; nt++) {
        const int col = h * D_DIM + nt * 8 + 2 * c;
        *(float2*)&ctx[((long)b * S_LEN + r0) * E_DIM + col] =
            make_float2(O[nt][0] * inv0, O[nt][1] * inv0);
        *(float2*)&ctx[((long)b * S_LEN + r0 + 8) * E_DIM + col] =
            make_float2(O[nt][2] * inv1, O[nt][3] * inv1);
    }
}

// ---------------------------------------------------------------------------
extern "C" void kernel_launch(void* const* d_in, const int* in_sizes, int n_in,
                              void* d_out, int out_size) {
    const float* q = (const float*)d_in[0];
    const float* k = (const float*)d_in[1];
    const float* v = (const float*)d_in[2];
    const int* mask = (const int*)d_in[3];
    const float* Wq = (const float*)d_in[4];
    const float* bq = (const float*)d_in[5];
    const float* Wk = (const float*)d_in[6];
    const float* bk = (const float*)d_in[7];
    const float* Wv = (const float*)d_in[8];
    const float* bv = (const float*)d_in[9];
    const float* Wo = (const float*)d_in[10];
    const float* bo = (const float*)d_in[11];

    float *Qh, *Kh, *Vh, *Ctx;
    cudaGetSymbolAddress((void**)&Qh, g_Qh);
    cudaGetSymbolAddress((void**)&Kh, g_Kh);
    cudaGetSymbolAddress((void**)&Vh, g_Vh);
    cudaGetSymbolAddress((void**)&Ctx, g_ctx);

    const int gemm_smem = STAGE_WORDS * 2 * sizeof(float);  // 55296 B
    cudaFuncSetAttribute(gemm_tc<true>, cudaFuncAttributeMaxDynamicSharedMemorySize, gemm_smem);
    cudaFuncSetAttribute(gemm_tc<false>, cudaFuncAttributeMaxDynamicSharedMemorySize, gemm_smem);

    // merged Q/K/V projections
    gemm_tc<true><<<dim3(E_DIM / 64, M_ROWS / 128, 3), 256, gemm_smem>>>(
        q, k, v, Wq, Wk, Wv, bq, bk, bv, Qh, Kh, Vh);

    attn_f16<<<dim3(S_LEN / 64, H_NUM, B_NUM), 128>>>(mask, Qh, Kh, Vh, Ctx);

    gemm_tc<false><<<dim3(E_DIM / 64, M_ROWS / 128, 1), 256, gemm_smem>>>(
        Ctx, Ctx, Ctx, Wo, Wo, Wo, bo, bo, bo, (float*)d_out, (float*)d_out,
        (float*)d_out);
}

// round 8
// speedup vs baseline: 2.2439x; 1.6734x over previous
#include <cuda_runtime.h>
#include <cuda_bf16.h>
#include <cuda_fp16.h>
#include <math.h>
#include <stdint.h>

#define E_DIM 768
#define H_NUM 12
#define D_DIM 64
#define B_NUM 4
#define S_LEN 2048
#define M_ROWS (B_NUM * S_LEN)   // 8192
#define ME (M_ROWS * E_DIM)      // 6291456
#define WE (E_DIM * E_DIM)       // 589824

// Scratch (static device globals: allocation-free)
__device__ __align__(16) __half g_Xh[3ll * ME];                      // q,k,v half
__device__ __align__(16) __half g_Wt[4ll * WE];                      // Wq,Wk,Wv,Wo transposed [n][k] half
__device__ __align__(16) __half g_Qh[B_NUM * H_NUM * S_LEN * D_DIM]; // [B,H,S,D]
__device__ __align__(16) __half g_Kh[B_NUM * H_NUM * S_LEN * D_DIM];
__device__ __align__(16) __half g_Vh[B_NUM * H_NUM * S_LEN * D_DIM];
__device__ __align__(16) __half g_ctx[ME];                           // [B,S,E] half

// ---------------------------------------------------------------------------
// helpers
// ---------------------------------------------------------------------------
__device__ __forceinline__ void mma_f16(float* d, uint32_t a0, uint32_t a1,
                                        uint32_t a2, uint32_t a3, uint32_t b0,
                                        uint32_t b1) {
    asm volatile(
        "mma.sync.aligned.m16n8k16.row.col.f32.f16.f16.f32 "
        "{%0,%1,%2,%3}, {%4,%5,%6,%7}, {%8,%9}, {%0,%1,%2,%3};\n"
        : "+f"(d[0]), "+f"(d[1]), "+f"(d[2]), "+f"(d[3])
        : "r"(a0), "r"(a1), "r"(a2), "r"(a3), "r"(b0), "r"(b1));
}

__device__ __forceinline__ void ldsm_x2_t(uint32_t& r0, uint32_t& r1,
                                          uint32_t addr) {
    asm volatile(
        "ldmatrix.sync.aligned.m8n8.x2.trans.shared.b16 {%0,%1}, [%2];"
        : "=r"(r0), "=r"(r1) : "r"(addr));
}

__device__ __forceinline__ float ex2(float x) {
    float y;
    asm("ex2.approx.ftz.f32 %0, %1;" : "=f"(y) : "f"(x));
    return y;
}

__device__ __forceinline__ uint32_t pack_h2(float lo, float hi) {
    __half2 h = __floats2half2_rn(lo, hi);
    return *(uint32_t*)&h;
}

__device__ __forceinline__ void cp16(uint32_t dst_smem, const void* src) {
    asm volatile("cp.async.ca.shared.global [%0], [%1], 16;\n"
                 :: "r"(dst_smem), "l"(src));
}
#define CP_COMMIT() asm volatile("cp.async.commit_group;\n")
#define CP_WAIT1()  asm volatile("cp.async.wait_group 1;\n")
#define CP_WAIT0()  asm volatile("cp.async.wait_group 0;\n")

// ---------------------------------------------------------------------------
// Convert kernels
// ---------------------------------------------------------------------------
__global__ __launch_bounds__(256) void cvt_x(const float* __restrict__ q,
                                             const float* __restrict__ k,
                                             const float* __restrict__ v) {
    const int z = blockIdx.y;
    const float* X = (z == 0) ? q : (z == 1) ? k : v;
    __half* o = g_Xh + (long)z * ME;
    const long i = ((long)blockIdx.x * 256 + threadIdx.x) * 4;
    float4 f = *(const float4*)&X[i];
    uint2 u;
    u.x = pack_h2(f.x, f.y);
    u.y = pack_h2(f.z, f.w);
    *(uint2*)&o[i] = u;
}

__global__ __launch_bounds__(256) void cvt_wt(const float* __restrict__ Wq,
                                              const float* __restrict__ Wk,
                                              const float* __restrict__ Wv,
                                              const float* __restrict__ Wo) {
    __shared__ float t[32][33];
    const int z = blockIdx.z;
    const float* W = (z == 0) ? Wq : (z == 1) ? Wk : (z == 2) ? Wv : Wo;
    __half* Wt = g_Wt + (long)z * WE;
    const int tx = threadIdx.x, ty = threadIdx.y;
    const int kb = blockIdx.x * 32, nb = blockIdx.y * 32;
#pragma unroll
    for (int i = 0; i < 4; i++)
        t[ty + i * 8][tx] = W[(long)(kb + ty + i * 8) * E_DIM + nb + tx];
    __syncthreads();
#pragma unroll
    for (int i = 0; i < 4; i++)
        Wt[(long)(nb + ty + i * 8) * E_DIM + kb + tx] =
            __float2half(t[tx][ty + i * 8]);
}

// ---------------------------------------------------------------------------
// fp16 tensor-core GEMM, cp.async double-buffered.
// Block tile 128x128, BK=32, 256 threads (8 warps 2x4 -> warp tile 32x64).
// A: Xh [m][k] half.  B: Wt [n][k] half.  Both padded to stride 40 halves.
// HEADS_OUT: half out scattered to [B,H,S,D]; else float out (+bias) to d_out.
// ---------------------------------------------------------------------------
#define BK16 32
#define LDH 40                        // halves
#define A_HALVES (128 * LDH)          // 5120
#define STG_HALVES (2 * A_HALVES)     // 10240 halves = 20480 B per stage

__device__ __forceinline__ void g16_issue(uint32_t sbase, const __half* __restrict__ X,
                                          const __half* __restrict__ Wt, int m0,
                                          int n0, int k0, int tid) {
    // A: 512 16B-chunks (128 rows x 4), B: 512 chunks
#pragma unroll
    for (int half_sel = 0; half_sel < 2; half_sel++) {
        const int ch = tid + half_sel * 256;
        const int r = ch >> 2, o = (ch & 3) * 8;  // o in halves
        cp16(sbase + (uint32_t)(r * LDH + o) * 2,
             X + (long)(m0 + r) * E_DIM + k0 + o);
        cp16(sbase + (uint32_t)(A_HALVES + r * LDH + o) * 2,
             Wt + (long)(n0 + r) * E_DIM + k0 + o);
    }
}

template <bool HEADS_OUT>
__global__ __launch_bounds__(256) void gemm_f16(
    const __half* __restrict__ Abase, const __half* __restrict__ Wtbase,
    const float* __restrict__ bias0, const float* __restrict__ bias1,
    const float* __restrict__ bias2, void* __restrict__ outv) {
    __shared__ __half gsm[2 * STG_HALVES];

    const int z = blockIdx.z;
    const __half* X = Abase + (long)z * ME;
    const __half* Wt = Wtbase + (long)z * WE;
    const float* bias = (z == 0) ? bias0 : (z == 1) ? bias1 : bias2;

    const int tid = threadIdx.x;
    const int w = tid >> 5, lane = tid & 31;
    const int wm = w >> 1, wn = w & 1;
    const int g = lane >> 2, c = lane & 3;
    const int m0 = blockIdx.y * 128, n0 = blockIdx.x * 128;

    const uint32_t sbase = (uint32_t)__cvta_generic_to_shared(gsm);

    float acc[2][8][4];
#pragma unroll
    for (int mt = 0; mt < 2; mt++)
#pragma unroll
        for (int nt = 0; nt < 8; nt++)
#pragma unroll
            for (int j = 0; j < 4; j++) acc[mt][nt][j] = 0.0f;

    g16_issue(sbase, X, Wt, m0, n0, 0, tid);
    CP_COMMIT();

    const int NT = E_DIM / BK16;  // 24
    for (int t = 0; t < NT; t++) {
        if (t < NT - 1) {
            g16_issue(sbase + (uint32_t)(((t + 1) & 1) * STG_HALVES * 2), X, Wt,
                      m0, n0, (t + 1) * BK16, tid);
            CP_COMMIT();
            CP_WAIT1();
        } else {
            CP_WAIT0();
        }
        __syncthreads();

        const __half* As = gsm + (t & 1) * STG_HALVES;
        const __half* Bs = As + A_HALVES;

#pragma unroll
        for (int ks = 0; ks < 2; ks++) {
            uint32_t a[2][4];
#pragma unroll
            for (int mt = 0; mt < 2; mt++) {
                const __half* ap =
                    &As[(wm * 32 + mt * 16 + g) * LDH + ks * 16 + 2 * c];
                a[mt][0] = *(const uint32_t*)ap;
                a[mt][1] = *(const uint32_t*)(ap + 8 * LDH);
                a[mt][2] = *(const uint32_t*)(ap + 8);
                a[mt][3] = *(const uint32_t*)(ap + 8 * LDH + 8);
            }
#pragma unroll
            for (int nt = 0; nt < 8; nt++) {
                const __half* bp =
                    &Bs[(wn * 64 + nt * 8 + g) * LDH + ks * 16 + 2 * c];
                const uint32_t b0 = *(const uint32_t*)bp;
                const uint32_t b1 = *(const uint32_t*)(bp + 8);
                mma_f16(acc[0][nt], a[0][0], a[0][1], a[0][2], a[0][3], b0, b1);
                mma_f16(acc[1][nt], a[1][0], a[1][1], a[1][2], a[1][3], b0, b1);
            }
        }
        __syncthreads();
    }

    // Epilogue
#pragma unroll
    for (int mt = 0; mt < 2; mt++) {
        const int r0 = m0 + wm * 32 + mt * 16 + g;
#pragma unroll
        for (int nt = 0; nt < 8; nt++) {
            const int col = n0 + wn * 64 + nt * 8 + 2 * c;
            const float bb0 = bias[col], bb1 = bias[col + 1];
            const float v00 = acc[mt][nt][0] + bb0;
            const float v01 = acc[mt][nt][1] + bb1;
            const float v10 = acc[mt][nt][2] + bb0;
            const float v11 = acc[mt][nt][3] + bb1;
            if (HEADS_OUT) {
                __half* out = (__half*)outv;
                const int hh = col >> 6, d = col & 63;
                const int b0i = r0 >> 11, s0 = r0 & 2047;
                const int r1 = r0 + 8;
                const int b1i = r1 >> 11, s1 = r1 & 2047;
                *(uint32_t*)&out[((long)(b0i * H_NUM + hh) * S_LEN + s0) * D_DIM + d] =
                    pack_h2(v00, v01);
                *(uint32_t*)&out[((long)(b1i * H_NUM + hh) * S_LEN + s1) * D_DIM + d] =
                    pack_h2(v10, v11);
            } else {
                float* out = (float*)outv;
                *(float2*)&out[(long)r0 * E_DIM + col] = make_float2(v00, v01);
                *(float2*)&out[(long)(r0 + 8) * E_DIM + col] = make_float2(v10, v11);
            }
        }
    }
}

// ---------------------------------------------------------------------------
// fp16 flash attention. Block = 4 warps, Br=64, Bc=64, D=64, half in/out.
// Ks,Vs both [key][d] half (stride 72, direct uint4 copies). QK B-frags via
// LDS.32 pairs; PV B-frags via ldmatrix.x2.trans. P stays in registers.
// ---------------------------------------------------------------------------
#define SCALE2 (0.125f * 1.44269504088896f)  // 1/sqrt(64) * log2(e)
#define KST 72

__global__ __launch_bounds__(128) void attn_f16(const int* __restrict__ mask,
                                                const __half* __restrict__ Qh,
                                                const __half* __restrict__ Kh,
                                                const __half* __restrict__ Vh,
                                                __half* __restrict__ ctx) {
    __shared__ __half Ks[64 * KST];
    __shared__ __half Vs[64 * KST];
    __shared__ float biasS[64];

    const int b = blockIdx.z, h = blockIdx.y;
    const int q0 = blockIdx.x * 64;
    const int tid = threadIdx.x;
    const int lane = tid & 31, w = tid >> 5;
    const int g = lane >> 2, c = lane & 3;

    const long base = (long)(b * H_NUM + h) * S_LEN * D_DIM;
    const __half* Q = Qh + base;
    const __half* K = Kh + base;
    const __half* V = Vh + base;

    const uint32_t vs_addr = (uint32_t)__cvta_generic_to_shared(Vs);

    // Q A-fragments (pre-scaled, fp16)
    uint32_t aq[4][4];
    {
        const __half* q_r0 = Q + (long)(q0 + w * 16 + g) * D_DIM;
        const __half* q_r1 = q_r0 + 8 * D_DIM;
#pragma unroll
        for (int ks = 0; ks < 4; ks++) {
            float2 p0 = __half22float2(*(const __half2*)&q_r0[ks * 16 + 2 * c]);
            float2 p1 = __half22float2(*(const __half2*)&q_r1[ks * 16 + 2 * c]);
            float2 p2 = __half22float2(*(const __half2*)&q_r0[ks * 16 + 2 * c + 8]);
            float2 p3 = __half22float2(*(const __half2*)&q_r1[ks * 16 + 2 * c + 8]);
            aq[ks][0] = pack_h2(p0.x * SCALE2, p0.y * SCALE2);
            aq[ks][1] = pack_h2(p1.x * SCALE2, p1.y * SCALE2);
            aq[ks][2] = pack_h2(p2.x * SCALE2, p2.y * SCALE2);
            aq[ks][3] = pack_h2(p3.x * SCALE2, p3.y * SCALE2);
        }
    }

    float O[8][4];
#pragma unroll
    for (int nt = 0; nt < 8; nt++)
#pragma unroll
        for (int j = 0; j < 4; j++) O[nt][j] = 0.0f;
    float mm0 = -1e30f, mm1 = -1e30f, l0 = 0.0f, l1 = 0.0f;

    for (int k0 = 0; k0 < S_LEN; k0 += 64) {
        __syncthreads();
        // K,V tiles: 64 rows x 64 halves = 512 16B-chunks; 128 threads x 4
#pragma unroll
        for (int i = 0; i < 4; i++) {
            const int ch = i * 128 + tid;
            const int rr = ch >> 3, oo = (ch & 7) * 8;
            *(uint4*)&Ks[rr * KST + oo] =
                *(const uint4*)&K[(long)(k0 + rr) * D_DIM + oo];
            *(uint4*)&Vs[rr * KST + oo] =
                *(const uint4*)&V[(long)(k0 + rr) * D_DIM + oo];
        }
        if (tid < 64)
            biasS[tid] = mask[b * S_LEN + k0 + tid] ? 0.0f : -1.442695e9f;
        __syncthreads();

        // S = (Q*scale) K^T
        float S[8][4];
#pragma unroll
        for (int nt = 0; nt < 8; nt++)
#pragma unroll
            for (int j = 0; j < 4; j++) S[nt][j] = 0.0f;

#pragma unroll
        for (int ks = 0; ks < 4; ks++) {
#pragma unroll
            for (int nt = 0; nt < 8; nt++) {
                const __half* kp = &Ks[(nt * 8 + g) * KST + ks * 16 + 2 * c];
                const uint32_t b0 = *(const uint32_t*)kp;
                const uint32_t b1 = *(const uint32_t*)(kp + 8);
                mma_f16(S[nt], aq[ks][0], aq[ks][1], aq[ks][2], aq[ks][3], b0, b1);
            }
        }

        // mask bias + online softmax
        float mx0 = -1e30f, mx1 = -1e30f;
#pragma unroll
        for (int nt = 0; nt < 8; nt++) {
            const float bb0 = biasS[nt * 8 + 2 * c];
            const float bb1 = biasS[nt * 8 + 2 * c + 1];
            S[nt][0] += bb0;
            S[nt][1] += bb1;
            S[nt][2] += bb0;
            S[nt][3] += bb1;
            mx0 = fmaxf(mx0, fmaxf(S[nt][0], S[nt][1]));
            mx1 = fmaxf(mx1, fmaxf(S[nt][2], S[nt][3]));
        }
        mx0 = fmaxf(mx0, __shfl_xor_sync(0xffffffffu, mx0, 1));
        mx0 = fmaxf(mx0, __shfl_xor_sync(0xffffffffu, mx0, 2));
        mx1 = fmaxf(mx1, __shfl_xor_sync(0xffffffffu, mx1, 1));
        mx1 = fmaxf(mx1, __shfl_xor_sync(0xffffffffu, mx1, 2));

        const float M0 = fmaxf(mm0, mx0), M1 = fmaxf(mm1, mx1);
        const float a0 = ex2(mm0 - M0), a1 = ex2(mm1 - M1);
        mm0 = M0;
        mm1 = M1;

        float s0 = 0.0f, s1 = 0.0f;
        uint32_t Pp[8][2];
#pragma unroll
        for (int nt = 0; nt < 8; nt++) {
            S[nt][0] = ex2(S[nt][0] - M0);
            S[nt][1] = ex2(S[nt][1] - M0);
            S[nt][2] = ex2(S[nt][2] - M1);
            S[nt][3] = ex2(S[nt][3] - M1);
            s0 += S[nt][0] + S[nt][1];
            s1 += S[nt][2] + S[nt][3];
            Pp[nt][0] = pack_h2(S[nt][0], S[nt][1]);
            Pp[nt][1] = pack_h2(S[nt][2], S[nt][3]);
        }
        s0 += __shfl_xor_sync(0xffffffffu, s0, 1);
        s0 += __shfl_xor_sync(0xffffffffu, s0, 2);
        s1 += __shfl_xor_sync(0xffffffffu, s1, 1);
        s1 += __shfl_xor_sync(0xffffffffu, s1, 2);
        l0 = l0 * a0 + s0;
        l1 = l1 * a1 + s1;

#pragma unroll
        for (int nt = 0; nt < 8; nt++) {
            O[nt][0] *= a0;
            O[nt][1] *= a0;
            O[nt][2] *= a1;
            O[nt][3] *= a1;
        }

        // O += P @ V ; B-frags via ldmatrix.trans on Vs [key][d]
#pragma unroll
        for (int ks = 0; ks < 4; ks++) {
            const uint32_t rowa =
                vs_addr + (uint32_t)(((ks * 16 + (lane & 15)) * KST) * 2);
#pragma unroll
            for (int nt = 0; nt < 8; nt++) {
                uint32_t b0, b1;
                ldsm_x2_t(b0, b1, rowa + nt * 16);
                mma_f16(O[nt], Pp[2 * ks][0], Pp[2 * ks][1], Pp[2 * ks + 1][0],
                        Pp[2 * ks + 1][1], b0, b1);
            }
        }
    }

    // epilogue: ctx half
    const float inv0 = 1.0f / l0, inv1 = 1.0f / l1;
    const int r0 = q0 + w * 16 + g;
#pragma unroll
    for (int nt = 0; nt < 8; nt++) {
        const int col = h * D_DIM + nt * 8 + 2 * c;
        *(uint32_t*)&ctx[((long)b * S_LEN + r0) * E_DIM + col] =
            pack_h2(O[nt][0] * inv0, O[nt][1] * inv0);
        *(uint32_t*)&ctx[((long)b * S_LEN + r0 + 8) * E_DIM + col] =
            pack_h2(O[nt][2] * inv1, O[nt][3] * inv1);
    }
}

// ---------------------------------------------------------------------------
extern "C" void kernel_launch(void* const* d_in, const int* in_sizes, int n_in,
                              void* d_out, int out_size) {
    const float* q = (const float*)d_in[0];
    const float* k = (const float*)d_in[1];
    const float* v = (const float*)d_in[2];
    const int* mask = (const int*)d_in[3];
    const float* Wq = (const float*)d_in[4];
    const float* bq = (const float*)d_in[5];
    const float* Wk = (const float*)d_in[6];
    const float* bk = (const float*)d_in[7];
    const float* Wv = (const float*)d_in[8];
    const float* bv = (const float*)d_in[9];
    const float* Wo = (const float*)d_in[10];
    const float* bo = (const float*)d_in[11];

    __half *Xh, *Wt, *Qh, *Kh, *Vh, *Ctx;
    cudaGetSymbolAddress((void**)&Xh, g_Xh);
    cudaGetSymbolAddress((void**)&Wt, g_Wt);
    cudaGetSymbolAddress((void**)&Qh, g_Qh);
    cudaGetSymbolAddress((void**)&Kh, g_Kh);
    cudaGetSymbolAddress((void**)&Vh, g_Vh);
    cudaGetSymbolAddress((void**)&Ctx, g_ctx);

    // converts
    cvt_x<<<dim3(ME / 1024, 3), 256>>>(q, k, v);
    cvt_wt<<<dim3(24, 24, 4), dim3(32, 8)>>>(Wq, Wk, Wv, Wo);

    // Q/K/V projections (one launch per output buffer)
    gemm_f16<true><<<dim3(6, 64, 1), 256>>>(Xh, Wt, bq, bq, bq, Qh);
    gemm_f16<true><<<dim3(6, 64, 1), 256>>>(Xh + (long)ME, Wt + (long)WE, bk,
                                            bk, bk, Kh);
    gemm_f16<true><<<dim3(6, 64, 1), 256>>>(Xh + 2ll * ME, Wt + 2ll * WE, bv,
                                            bv, bv, Vh);

    attn_f16<<<dim3(S_LEN / 64, H_NUM, B_NUM), 128>>>(mask, Qh, Kh, Vh, Ctx);

    gemm_f16<false><<<dim3(6, 64, 1), 256>>>(Ctx, Wt + 3ll * WE, bo, bo, bo,
                                             d_out);
}

// round 10
// speedup vs baseline: 2.6373x; 1.1753x over previous
#include <cuda_runtime.h>
#include <cuda_bf16.h>
#include <cuda_fp16.h>
#include <math.h>
#include <stdint.h>

#define E_DIM 768
#define H_NUM 12
#define D_DIM 64
#define B_NUM 4
#define S_LEN 2048
#define M_ROWS (B_NUM * S_LEN)   // 8192
#define ME (M_ROWS * E_DIM)      // 6291456
#define WE (E_DIM * E_DIM)       // 589824

// Scratch (static device globals: allocation-free)
__device__ __align__(16) __half g_Xh[3ll * ME];                      // q,k,v half
__device__ __align__(16) __half g_Wt[4ll * WE];                      // W transposed [n][k] half
__device__ __align__(16) __half g_Qh[B_NUM * H_NUM * S_LEN * D_DIM]; // [B,H,S,D]
__device__ __align__(16) __half g_Kh[B_NUM * H_NUM * S_LEN * D_DIM];
__device__ __align__(16) __half g_Vh[B_NUM * H_NUM * S_LEN * D_DIM];
__device__ __align__(16) __half g_ctx[ME];                           // [B,S,E] half

// ---------------------------------------------------------------------------
// helpers
// ---------------------------------------------------------------------------
__device__ __forceinline__ void mma_f16(float* d, uint32_t a0, uint32_t a1,
                                        uint32_t a2, uint32_t a3, uint32_t b0,
                                        uint32_t b1) {
    asm volatile(
        "mma.sync.aligned.m16n8k16.row.col.f32.f16.f16.f32 "
        "{%0,%1,%2,%3}, {%4,%5,%6,%7}, {%8,%9}, {%0,%1,%2,%3};\n"
        : "+f"(d[0]), "+f"(d[1]), "+f"(d[2]), "+f"(d[3])
        : "r"(a0), "r"(a1), "r"(a2), "r"(a3), "r"(b0), "r"(b1));
}

__device__ __forceinline__ void ldsm_x2_t(uint32_t& r0, uint32_t& r1,
                                          uint32_t addr) {
    asm volatile(
        "ldmatrix.sync.aligned.m8n8.x2.trans.shared.b16 {%0,%1}, [%2];"
        : "=r"(r0), "=r"(r1) : "r"(addr));
}

__device__ __forceinline__ float ex2(float x) {
    float y;
    asm("ex2.approx.ftz.f32 %0, %1;" : "=f"(y) : "f"(x));
    return y;
}

__device__ __forceinline__ uint32_t pack_h2(float lo, float hi) {
    __half2 h = __floats2half2_rn(lo, hi);
    return *(uint32_t*)&h;
}

__device__ __forceinline__ void cp16(uint32_t dst_smem, const void* src) {
    asm volatile("cp.async.ca.shared.global [%0], [%1], 16;\n"
                 :: "r"(dst_smem), "l"(src));
}
#define CP_COMMIT() asm volatile("cp.async.commit_group;\n")
#define CP_WAIT2()  asm volatile("cp.async.wait_group 2;\n")
#define CP_WAIT1()  asm volatile("cp.async.wait_group 1;\n")
#define CP_WAIT0()  asm volatile("cp.async.wait_group 0;\n")

// ---------------------------------------------------------------------------
// Convert kernels
// ---------------------------------------------------------------------------
__global__ __launch_bounds__(256) void cvt_x(const float* __restrict__ q,
                                             const float* __restrict__ k,
                                             const float* __restrict__ v) {
    const int z = blockIdx.y;
    const float* X = (z == 0) ? q : (z == 1) ? k : v;
    __half* o = g_Xh + (long)z * ME;
    const long i = ((long)blockIdx.x * 256 + threadIdx.x) * 4;
    float4 f = *(const float4*)&X[i];
    uint2 u;
    u.x = pack_h2(f.x, f.y);
    u.y = pack_h2(f.z, f.w);
    *(uint2*)&o[i] = u;
}

__global__ __launch_bounds__(256) void cvt_wt(const float* __restrict__ Wq,
                                              const float* __restrict__ Wk,
                                              const float* __restrict__ Wv,
                                              const float* __restrict__ Wo) {
    __shared__ float t[32][33];
    const int z = blockIdx.z;
    const float* W = (z == 0) ? Wq : (z == 1) ? Wk : (z == 2) ? Wv : Wo;
    __half* Wt = g_Wt + (long)z * WE;
    const int tx = threadIdx.x, ty = threadIdx.y;
    const int kb = blockIdx.x * 32, nb = blockIdx.y * 32;
#pragma unroll
    for (int i = 0; i < 4; i++)
        t[ty + i * 8][tx] = W[(long)(kb + ty + i * 8) * E_DIM + nb + tx];
    __syncthreads();
#pragma unroll
    for (int i = 0; i < 4; i++)
        Wt[(long)(nb + ty + i * 8) * E_DIM + kb + tx] =
            __float2half(t[tx][ty + i * 8]);
}

// ---------------------------------------------------------------------------
// fp16 tensor-core GEMM, cp.async 3-stage pipelined.
// Block tile 128x128, BK=32, 256 threads (8 warps 2x4 -> warp tile 32x64).
// A: Xh [m][k] half.  B: Wt [n][k] half.  Both padded to stride 40 halves.
// ---------------------------------------------------------------------------
#define BK16 32
#define LDH 40                        // halves
#define A_HALVES (128 * LDH)          // 5120
#define STG_HALVES (2 * A_HALVES)     // 10240 halves = 20480 B per stage
#define GEMM_SMEM (3 * STG_HALVES * 2)  // 61440 B

__device__ __forceinline__ void g16_issue(uint32_t sbase, const __half* __restrict__ X,
                                          const __half* __restrict__ Wt, int m0,
                                          int n0, int k0, int tid) {
#pragma unroll
    for (int half_sel = 0; half_sel < 2; half_sel++) {
        const int ch = tid + half_sel * 256;
        const int r = ch >> 2, o = (ch & 3) * 8;  // o in halves
        cp16(sbase + (uint32_t)(r * LDH + o) * 2,
             X + (long)(m0 + r) * E_DIM + k0 + o);
        cp16(sbase + (uint32_t)(A_HALVES + r * LDH + o) * 2,
             Wt + (long)(n0 + r) * E_DIM + k0 + o);
    }
}

template <bool HEADS_OUT>
__global__ __launch_bounds__(256) void gemm_f16(
    const __half* __restrict__ Abase, const __half* __restrict__ Wtbase,
    const float* __restrict__ bias0, const float* __restrict__ bias1,
    const float* __restrict__ bias2, void* __restrict__ out0v,
    void* __restrict__ out1v, void* __restrict__ out2v) {
    extern __shared__ __half gsm[];

    const int z = blockIdx.z;
    const __half* X = Abase + (long)z * ME;
    const __half* Wt = Wtbase + (long)z * WE;
    const float* bias = (z == 0) ? bias0 : (z == 1) ? bias1 : bias2;
    void* outv = (z == 0) ? out0v : (z == 1) ? out1v : out2v;

    const int tid = threadIdx.x;
    const int w = tid >> 5, lane = tid & 31;
    const int wm = w >> 1, wn = w & 1;
    const int g = lane >> 2, c = lane & 3;
    const int m0 = blockIdx.y * 128, n0 = blockIdx.x * 128;

    const uint32_t sbase = (uint32_t)__cvta_generic_to_shared(gsm);

    float acc[2][8][4];
#pragma unroll
    for (int mt = 0; mt < 2; mt++)
#pragma unroll
        for (int nt = 0; nt < 8; nt++)
#pragma unroll
            for (int j = 0; j < 4; j++) acc[mt][nt][j] = 0.0f;

    const int NT = E_DIM / BK16;  // 24
    g16_issue(sbase, X, Wt, m0, n0, 0, tid);
    CP_COMMIT();
    g16_issue(sbase + (uint32_t)(STG_HALVES * 2), X, Wt, m0, n0, BK16, tid);
    CP_COMMIT();

    int cs = 0, is = 2;  // compute stage, next issue stage
    for (int t = 0; t < NT; t++) {
        if (t + 2 < NT) {
            g16_issue(sbase + (uint32_t)(is * STG_HALVES * 2), X, Wt, m0, n0,
                      (t + 2) * BK16, tid);
            CP_COMMIT();
            is = (is == 2) ? 0 : is + 1;
            CP_WAIT2();
        } else if (t + 1 < NT) {
            CP_WAIT1();
        } else {
            CP_WAIT0();
        }
        __syncthreads();

        const __half* As = gsm + cs * STG_HALVES;
        const __half* Bs = As + A_HALVES;
        cs = (cs == 2) ? 0 : cs + 1;

#pragma unroll
        for (int ks = 0; ks < 2; ks++) {
            uint32_t a[2][4];
#pragma unroll
            for (int mt = 0; mt < 2; mt++) {
                const __half* ap =
                    &As[(wm * 32 + mt * 16 + g) * LDH + ks * 16 + 2 * c];
                a[mt][0] = *(const uint32_t*)ap;
                a[mt][1] = *(const uint32_t*)(ap + 8 * LDH);
                a[mt][2] = *(const uint32_t*)(ap + 8);
                a[mt][3] = *(const uint32_t*)(ap + 8 * LDH + 8);
            }
#pragma unroll
            for (int nt = 0; nt < 8; nt++) {
                const __half* bp =
                    &Bs[(wn * 64 + nt * 8 + g) * LDH + ks * 16 + 2 * c];
                const uint32_t b0 = *(const uint32_t*)bp;
                const uint32_t b1 = *(const uint32_t*)(bp + 8);
                mma_f16(acc[0][nt], a[0][0], a[0][1], a[0][2], a[0][3], b0, b1);
                mma_f16(acc[1][nt], a[1][0], a[1][1], a[1][2], a[1][3], b0, b1);
            }
        }
        __syncthreads();
    }

    // Epilogue
#pragma unroll
    for (int mt = 0; mt < 2; mt++) {
        const int r0 = m0 + wm * 32 + mt * 16 + g;
#pragma unroll
        for (int nt = 0; nt < 8; nt++) {
            const int col = n0 + wn * 64 + nt * 8 + 2 * c;
            const float bb0 = bias[col], bb1 = bias[col + 1];
            const float v00 = acc[mt][nt][0] + bb0;
            const float v01 = acc[mt][nt][1] + bb1;
            const float v10 = acc[mt][nt][2] + bb0;
            const float v11 = acc[mt][nt][3] + bb1;
            if (HEADS_OUT) {
                __half* out = (__half*)outv;
                const int hh = col >> 6, d = col & 63;
                const int b0i = r0 >> 11, s0 = r0 & 2047;
                const int r1 = r0 + 8;
                const int b1i = r1 >> 11, s1 = r1 & 2047;
                *(uint32_t*)&out[((long)(b0i * H_NUM + hh) * S_LEN + s0) * D_DIM + d] =
                    pack_h2(v00, v01);
                *(uint32_t*)&out[((long)(b1i * H_NUM + hh) * S_LEN + s1) * D_DIM + d] =
                    pack_h2(v10, v11);
            } else {
                float* out = (float*)outv;
                *(float2*)&out[(long)r0 * E_DIM + col] = make_float2(v00, v01);
                *(float2*)&out[(long)(r0 + 8) * E_DIM + col] = make_float2(v10, v11);
            }
        }
    }
}

// ---------------------------------------------------------------------------
// fp16 flash attention, cp.async double-buffered K/V/mask tiles.
// Block = 4 warps, Br=64, Bc=64, D=64, half in/out.
// QK B-frags via LDS.32 pairs; PV B-frags via ldmatrix.x2.trans.
// ---------------------------------------------------------------------------
#define SCALE2 (0.125f * 1.44269504088896f)  // 1/sqrt(64) * log2(e)
#define KST 72
#define TILE_HALVES (64 * KST)   // 4608

__global__ __launch_bounds__(128) void attn_f16(const int* __restrict__ mask,
                                                const __half* __restrict__ Qh,
                                                const __half* __restrict__ Kh,
                                                const __half* __restrict__ Vh,
                                                __half* __restrict__ ctx) {
    __shared__ __half KVs[2][2][TILE_HALVES];  // [stage][K=0/V=1]
    __shared__ int maskS[2][64];

    const int b = blockIdx.z, h = blockIdx.y;
    const int q0 = blockIdx.x * 64;
    const int tid = threadIdx.x;
    const int lane = tid & 31, w = tid >> 5;
    const int g = lane >> 2, c = lane & 3;

    const long base = (long)(b * H_NUM + h) * S_LEN * D_DIM;
    const __half* Q = Qh + base;
    const __half* K = Kh + base;
    const __half* V = Vh + base;
    const int* mrow = mask + b * S_LEN;

    const uint32_t kv_sb = (uint32_t)__cvta_generic_to_shared(&KVs[0][0][0]);
    const uint32_t mk_sb = (uint32_t)__cvta_generic_to_shared(&maskS[0][0]);

    // Q A-fragments (pre-scaled, fp16)
    uint32_t aq[4][4];
    {
        const __half* q_r0 = Q + (long)(q0 + w * 16 + g) * D_DIM;
        const __half* q_r1 = q_r0 + 8 * D_DIM;
#pragma unroll
        for (int ks = 0; ks < 4; ks++) {
            float2 p0 = __half22float2(*(const __half2*)&q_r0[ks * 16 + 2 * c]);
            float2 p1 = __half22float2(*(const __half2*)&q_r1[ks * 16 + 2 * c]);
            float2 p2 = __half22float2(*(const __half2*)&q_r0[ks * 16 + 2 * c + 8]);
            float2 p3 = __half22float2(*(const __half2*)&q_r1[ks * 16 + 2 * c + 8]);
            aq[ks][0] = pack_h2(p0.x * SCALE2, p0.y * SCALE2);
            aq[ks][1] = pack_h2(p1.x * SCALE2, p1.y * SCALE2);
            aq[ks][2] = pack_h2(p2.x * SCALE2, p2.y * SCALE2);
            aq[ks][3] = pack_h2(p3.x * SCALE2, p3.y * SCALE2);
        }
    }

    float O[8][4];
#pragma unroll
    for (int nt = 0; nt < 8; nt++)
#pragma unroll
        for (int j = 0; j < 4; j++) O[nt][j] = 0.0f;
    float mm0 = -1e30f, mm1 = -1e30f, l0 = 0.0f, l1 = 0.0f;

    auto issue_tile = [&](int kt, int st) {
        const int k0 = kt * 64;
        const uint32_t kb = kv_sb + (uint32_t)((st * 2) * TILE_HALVES * 2);
        const uint32_t vb = kb + (uint32_t)(TILE_HALVES * 2);
#pragma unroll
        for (int i = 0; i < 4; i++) {
            const int ch = i * 128 + tid;
            const int r = ch >> 3, o = (ch & 7) * 8;
            cp16(kb + (uint32_t)(r * KST + o) * 2, K + (long)(k0 + r) * D_DIM + o);
            cp16(vb + (uint32_t)(r * KST + o) * 2, V + (long)(k0 + r) * D_DIM + o);
        }
        if (tid < 16)
            cp16(mk_sb + (uint32_t)(st * 256 + tid * 16), mrow + k0 + tid * 4);
    };

    issue_tile(0, 0);
    CP_COMMIT();

    const int NTILES = S_LEN / 64;  // 32
    for (int t = 0; t < NTILES; t++) {
        if (t + 1 < NTILES) {
            issue_tile(t + 1, (t + 1) & 1);
            CP_COMMIT();
            CP_WAIT1();
        } else {
            CP_WAIT0();
        }
        __syncthreads();

        const int st = t & 1;
        const __half* Ks = &KVs[st][0][0];
        const uint32_t vs_addr =
            kv_sb + (uint32_t)((st * 2 + 1) * TILE_HALVES * 2);
        const int* mskp = &maskS[st][0];

        // S = (Q*scale) K^T
        float S[8][4];
#pragma unroll
        for (int nt = 0; nt < 8; nt++)
#pragma unroll
            for (int j = 0; j < 4; j++) S[nt][j] = 0.0f;

#pragma unroll
        for (int ks = 0; ks < 4; ks++) {
#pragma unroll
            for (int nt = 0; nt < 8; nt++) {
                const __half* kp = &Ks[(nt * 8 + g) * KST + ks * 16 + 2 * c];
                const uint32_t b0 = *(const uint32_t*)kp;
                const uint32_t b1 = *(const uint32_t*)(kp + 8);
                mma_f16(S[nt], aq[ks][0], aq[ks][1], aq[ks][2], aq[ks][3], b0, b1);
            }
        }

        // mask bias + online softmax
        float mx0 = -1e30f, mx1 = -1e30f;
#pragma unroll
        for (int nt = 0; nt < 8; nt++) {
            const float bb0 = mskp[nt * 8 + 2 * c] ? 0.0f : -1.442695e9f;
            const float bb1 = mskp[nt * 8 + 2 * c + 1] ? 0.0f : -1.442695e9f;
            S[nt][0] += bb0;
            S[nt][1] += bb1;
            S[nt][2] += bb0;
            S[nt][3] += bb1;
            mx0 = fmaxf(mx0, fmaxf(S[nt][0], S[nt][1]));
            mx1 = fmaxf(mx1, fmaxf(S[nt][2], S[nt][3]));
        }
        mx0 = fmaxf(mx0, __shfl_xor_sync(0xffffffffu, mx0, 1));
        mx0 = fmaxf(mx0, __shfl_xor_sync(0xffffffffu, mx0, 2));
        mx1 = fmaxf(mx1, __shfl_xor_sync(0xffffffffu, mx1, 1));
        mx1 = fmaxf(mx1, __shfl_xor_sync(0xffffffffu, mx1, 2));

        const float M0 = fmaxf(mm0, mx0), M1 = fmaxf(mm1, mx1);
        const float a0 = ex2(mm0 - M0), a1 = ex2(mm1 - M1);
        mm0 = M0;
        mm1 = M1;

        float s0 = 0.0f, s1 = 0.0f;
        uint32_t Pp[8][2];
#pragma unroll
        for (int nt = 0; nt < 8; nt++) {
            S[nt][0] = ex2(S[nt][0] - M0);
            S[nt][1] = ex2(S[nt][1] - M0);
            S[nt][2] = ex2(S[nt][2] - M1);
            S[nt][3] = ex2(S[nt][3] - M1);
            s0 += S[nt][0] + S[nt][1];
            s1 += S[nt][2] + S[nt][3];
            Pp[nt][0] = pack_h2(S[nt][0], S[nt][1]);
            Pp[nt][1] = pack_h2(S[nt][2], S[nt][3]);
        }
        s0 += __shfl_xor_sync(0xffffffffu, s0, 1);
        s0 += __shfl_xor_sync(0xffffffffu, s0, 2);
        s1 += __shfl_xor_sync(0xffffffffu, s1, 1);
        s1 += __shfl_xor_sync(0xffffffffu, s1, 2);
        l0 = l0 * a0 + s0;
        l1 = l1 * a1 + s1;

#pragma unroll
        for (int nt = 0; nt < 8; nt++) {
            O[nt][0] *= a0;
            O[nt][1] *= a0;
            O[nt][2] *= a1;
            O[nt][3] *= a1;
        }

        // O += P @ V ; B-frags via ldmatrix.trans on Vs [key][d]
#pragma unroll
        for (int ks = 0; ks < 4; ks++) {
            const uint32_t rowa =
                vs_addr + (uint32_t)(((ks * 16 + (lane & 15)) * KST) * 2);
#pragma unroll
            for (int nt = 0; nt < 8; nt++) {
                uint32_t b0, b1;
                ldsm_x2_t(b0, b1, rowa + nt * 16);
                mma_f16(O[nt], Pp[2 * ks][0], Pp[2 * ks][1], Pp[2 * ks + 1][0],
                        Pp[2 * ks + 1][1], b0, b1);
            }
        }
        __syncthreads();
    }

    // epilogue: ctx half
    const float inv0 = 1.0f / l0, inv1 = 1.0f / l1;
    const int r0 = q0 + w * 16 + g;
#pragma unroll
    for (int nt = 0; nt < 8; nt++) {
        const int col = h * D_DIM + nt * 8 + 2 * c;
        *(uint32_t*)&ctx[((long)b * S_LEN + r0) * E_DIM + col] =
            pack_h2(O[nt][0] * inv0, O[nt][1] * inv0);
        *(uint32_t*)&ctx[((long)b * S_LEN + r0 + 8) * E_DIM + col] =
            pack_h2(O[nt][2] * inv1, O[nt][3] * inv1);
    }
}

// ---------------------------------------------------------------------------
extern "C" void kernel_launch(void* const* d_in, const int* in_sizes, int n_in,
                              void* d_out, int out_size) {
    const float* q = (const float*)d_in[0];
    const float* k = (const float*)d_in[1];
    const float* v = (const float*)d_in[2];
    const int* mask = (const int*)d_in[3];
    const float* Wq = (const float*)d_in[4];
    const float* bq = (const float*)d_in[5];
    const float* Wk = (const float*)d_in[6];
    const float* bk = (const float*)d_in[7];
    const float* Wv = (const float*)d_in[8];
    const float* bv = (const float*)d_in[9];
    const float* Wo = (const float*)d_in[10];
    const float* bo = (const float*)d_in[11];

    __half *Xh, *Wt, *Qh, *Kh, *Vh, *Ctx;
    cudaGetSymbolAddress((void**)&Xh, g_Xh);
    cudaGetSymbolAddress((void**)&Wt, g_Wt);
    cudaGetSymbolAddress((void**)&Qh, g_Qh);
    cudaGetSymbolAddress((void**)&Kh, g_Kh);
    cudaGetSymbolAddress((void**)&Vh, g_Vh);
    cudaGetSymbolAddress((void**)&Ctx, g_ctx);

    cudaFuncSetAttribute(gemm_f16<true>,
                         cudaFuncAttributeMaxDynamicSharedMemorySize, GEMM_SMEM);
    cudaFuncSetAttribute(gemm_f16<false>,
                         cudaFuncAttributeMaxDynamicSharedMemorySize, GEMM_SMEM);

    // converts
    cvt_x<<<dim3(ME / 1024, 3), 256>>>(q, k, v);
    cvt_wt<<<dim3(24, 24, 4), dim3(32, 8)>>>(Wq, Wk, Wv, Wo);

    // merged Q/K/V projections
    gemm_f16<true><<<dim3(6, 64, 3), 256, GEMM_SMEM>>>(Xh, Wt, bq, bk, bv, Qh,
                                                       Kh, Vh);

    attn_f16<<<dim3(S_LEN / 64, H_NUM, B_NUM), 128>>>(mask, Qh, Kh, Vh, Ctx);

    gemm_f16<false><<<dim3(6, 64, 1), 256, GEMM_SMEM>>>(
        Ctx, Wt + 3ll * WE, bo, bo, bo, d_out, d_out, d_out);
}

// round 11
// speedup vs baseline: 2.8635x; 1.0858x over previous
#include <cuda_runtime.h>
#include <cuda_bf16.h>
#include <cuda_fp16.h>
#include <math.h>
#include <stdint.h>

#define E_DIM 768
#define H_NUM 12
#define D_DIM 64
#define B_NUM 4
#define S_LEN 2048
#define M_ROWS (B_NUM * S_LEN)   // 8192
#define ME (M_ROWS * E_DIM)      // 6291456
#define WE (E_DIM * E_DIM)       // 589824

// Scratch (static device globals: allocation-free)
__device__ __align__(16) __half g_Xh[3ll * ME];                      // q,k,v half
__device__ __align__(16) __half g_Wt[4ll * WE];                      // W transposed [n][k] half
__device__ __align__(16) __half g_Qh[B_NUM * H_NUM * S_LEN * D_DIM]; // [B,H,S,D]
__device__ __align__(16) __half g_Kh[B_NUM * H_NUM * S_LEN * D_DIM];
__device__ __align__(16) __half g_Vh[B_NUM * H_NUM * S_LEN * D_DIM];
__device__ __align__(16) __half g_ctx[ME];                           // [B,S,E] half

// ---------------------------------------------------------------------------
// helpers
// ---------------------------------------------------------------------------
__device__ __forceinline__ void mma_f16(float* d, uint32_t a0, uint32_t a1,
                                        uint32_t a2, uint32_t a3, uint32_t b0,
                                        uint32_t b1) {
    asm volatile(
        "mma.sync.aligned.m16n8k16.row.col.f32.f16.f16.f32 "
        "{%0,%1,%2,%3}, {%4,%5,%6,%7}, {%8,%9}, {%0,%1,%2,%3};\n"
        : "+f"(d[0]), "+f"(d[1]), "+f"(d[2]), "+f"(d[3])
        : "r"(a0), "r"(a1), "r"(a2), "r"(a3), "r"(b0), "r"(b1));
}

__device__ __forceinline__ void ldsm_x4(uint32_t& r0, uint32_t& r1,
                                        uint32_t& r2, uint32_t& r3,
                                        uint32_t addr) {
    asm volatile(
        "ldmatrix.sync.aligned.m8n8.x4.shared.b16 {%0,%1,%2,%3}, [%4];"
        : "=r"(r0), "=r"(r1), "=r"(r2), "=r"(r3) : "r"(addr));
}

__device__ __forceinline__ void ldsm_x4_t(uint32_t& r0, uint32_t& r1,
                                          uint32_t& r2, uint32_t& r3,
                                          uint32_t addr) {
    asm volatile(
        "ldmatrix.sync.aligned.m8n8.x4.trans.shared.b16 {%0,%1,%2,%3}, [%4];"
        : "=r"(r0), "=r"(r1), "=r"(r2), "=r"(r3) : "r"(addr));
}

__device__ __forceinline__ float ex2(float x) {
    float y;
    asm("ex2.approx.ftz.f32 %0, %1;" : "=f"(y) : "f"(x));
    return y;
}

__device__ __forceinline__ uint32_t pack_h2(float lo, float hi) {
    __half2 h = __floats2half2_rn(lo, hi);
    return *(uint32_t*)&h;
}

__device__ __forceinline__ void cp16(uint32_t dst_smem, const void* src) {
    asm volatile("cp.async.ca.shared.global [%0], [%1], 16;\n"
                 :: "r"(dst_smem), "l"(src));
}
#define CP_COMMIT() asm volatile("cp.async.commit_group;\n")
#define CP_WAIT2()  asm volatile("cp.async.wait_group 2;\n")
#define CP_WAIT1()  asm volatile("cp.async.wait_group 1;\n")
#define CP_WAIT0()  asm volatile("cp.async.wait_group 0;\n")

// ---------------------------------------------------------------------------
// Convert kernels
// ---------------------------------------------------------------------------
__global__ __launch_bounds__(256) void cvt_x(const float* __restrict__ q,
                                             const float* __restrict__ k,
                                             const float* __restrict__ v) {
    const int z = blockIdx.y;
    const float* X = (z == 0) ? q : (z == 1) ? k : v;
    __half* o = g_Xh + (long)z * ME;
    const long i = ((long)blockIdx.x * 256 + threadIdx.x) * 4;
    float4 f = *(const float4*)&X[i];
    uint2 u;
    u.x = pack_h2(f.x, f.y);
    u.y = pack_h2(f.z, f.w);
    *(uint2*)&o[i] = u;
}

__global__ __launch_bounds__(256) void cvt_wt(const float* __restrict__ Wq,
                                              const float* __restrict__ Wk,
                                              const float* __restrict__ Wv,
                                              const float* __restrict__ Wo) {
    __shared__ float t[32][33];
    const int z = blockIdx.z;
    const float* W = (z == 0) ? Wq : (z == 1) ? Wk : (z == 2) ? Wv : Wo;
    __half* Wt = g_Wt + (long)z * WE;
    const int tx = threadIdx.x, ty = threadIdx.y;
    const int kb = blockIdx.x * 32, nb = blockIdx.y * 32;
#pragma unroll
    for (int i = 0; i < 4; i++)
        t[ty + i * 8][tx] = W[(long)(kb + ty + i * 8) * E_DIM + nb + tx];
    __syncthreads();
#pragma unroll
    for (int i = 0; i < 4; i++)
        Wt[(long)(nb + ty + i * 8) * E_DIM + kb + tx] =
            __float2half(t[tx][ty + i * 8]);
}

// ---------------------------------------------------------------------------
// fp16 tensor-core GEMM, cp.async 3-stage pipelined, ldmatrix.x4 frag loads.
// Block tile 128x128, BK=32, 256 threads (8 warps 2x4 -> warp tile 32x64).
// A: Xh [m][k] half.  B: Wt [n][k] half.  Both padded to stride 40 halves.
// ---------------------------------------------------------------------------
#define BK16 32
#define LDH 40                        // halves
#define A_HALVES (128 * LDH)          // 5120
#define STG_HALVES (2 * A_HALVES)     // 10240 halves = 20480 B per stage
#define GEMM_SMEM (3 * STG_HALVES * 2)  // 61440 B

__device__ __forceinline__ void g16_issue(uint32_t sbase, const __half* __restrict__ X,
                                          const __half* __restrict__ Wt, int m0,
                                          int n0, int k0, int tid) {
#pragma unroll
    for (int half_sel = 0; half_sel < 2; half_sel++) {
        const int ch = tid + half_sel * 256;
        const int r = ch >> 2, o = (ch & 3) * 8;  // o in halves
        cp16(sbase + (uint32_t)(r * LDH + o) * 2,
             X + (long)(m0 + r) * E_DIM + k0 + o);
        cp16(sbase + (uint32_t)(A_HALVES + r * LDH + o) * 2,
             Wt + (long)(n0 + r) * E_DIM + k0 + o);
    }
}

template <bool HEADS_OUT>
__global__ __launch_bounds__(256) void gemm_f16(
    const __half* __restrict__ Abase, const __half* __restrict__ Wtbase,
    const float* __restrict__ bias0, const float* __restrict__ bias1,
    const float* __restrict__ bias2, void* __restrict__ out0v,
    void* __restrict__ out1v, void* __restrict__ out2v) {
    extern __shared__ __half gsm[];

    const int z = blockIdx.z;
    const __half* X = Abase + (long)z * ME;
    const __half* Wt = Wtbase + (long)z * WE;
    const float* bias = (z == 0) ? bias0 : (z == 1) ? bias1 : bias2;
    void* outv = (z == 0) ? out0v : (z == 1) ? out1v : out2v;

    const int tid = threadIdx.x;
    const int w = tid >> 5, lane = tid & 31;
    const int wm = w >> 1, wn = w & 1;
    const int g = lane >> 2, c = lane & 3;
    const int m0 = blockIdx.y * 128, n0 = blockIdx.x * 128;

    const uint32_t sbase = (uint32_t)__cvta_generic_to_shared(gsm);

    // ldmatrix per-lane address components
    const int arow_l = (lane & 7) + ((lane >> 3) & 1) * 8;  // + (lane>=16 -> col+8)
    const int acol_l = (lane >> 4) * 8;
    const int brow_l = (lane & 7) + (lane >> 4) * 8;
    const int bcol_l = ((lane >> 3) & 1) * 8;

    float acc[2][8][4];
#pragma unroll
    for (int mt = 0; mt < 2; mt++)
#pragma unroll
        for (int nt = 0; nt < 8; nt++)
#pragma unroll
            for (int j = 0; j < 4; j++) acc[mt][nt][j] = 0.0f;

    const int NT = E_DIM / BK16;  // 24
    g16_issue(sbase, X, Wt, m0, n0, 0, tid);
    CP_COMMIT();
    g16_issue(sbase + (uint32_t)(STG_HALVES * 2), X, Wt, m0, n0, BK16, tid);
    CP_COMMIT();

    int cs = 0, is = 2;  // compute stage, next issue stage
    for (int t = 0; t < NT; t++) {
        if (t + 2 < NT) {
            g16_issue(sbase + (uint32_t)(is * STG_HALVES * 2), X, Wt, m0, n0,
                      (t + 2) * BK16, tid);
            CP_COMMIT();
            is = (is == 2) ? 0 : is + 1;
            CP_WAIT2();
        } else if (t + 1 < NT) {
            CP_WAIT1();
        } else {
            CP_WAIT0();
        }
        __syncthreads();

        const uint32_t as_b = sbase + (uint32_t)(cs * STG_HALVES * 2);
        const uint32_t bs_b = as_b + (uint32_t)(A_HALVES * 2);
        cs = (cs == 2) ? 0 : cs + 1;

#pragma unroll
        for (int ks = 0; ks < 2; ks++) {
            uint32_t a[2][4];
#pragma unroll
            for (int mt = 0; mt < 2; mt++)
                ldsm_x4(a[mt][0], a[mt][1], a[mt][2], a[mt][3],
                        as_b + (uint32_t)(((wm * 32 + mt * 16 + arow_l) * LDH +
                                           ks * 16 + acol_l) * 2));
#pragma unroll
            for (int ntp = 0; ntp < 4; ntp++) {
                uint32_t b0, b1, b2, b3;
                ldsm_x4(b0, b1, b2, b3,
                        bs_b + (uint32_t)(((wn * 64 + ntp * 16 + brow_l) * LDH +
                                           ks * 16 + bcol_l) * 2));
                mma_f16(acc[0][2 * ntp], a[0][0], a[0][1], a[0][2], a[0][3], b0, b1);
                mma_f16(acc[1][2 * ntp], a[1][0], a[1][1], a[1][2], a[1][3], b0, b1);
                mma_f16(acc[0][2 * ntp + 1], a[0][0], a[0][1], a[0][2], a[0][3], b2, b3);
                mma_f16(acc[1][2 * ntp + 1], a[1][0], a[1][1], a[1][2], a[1][3], b2, b3);
            }
        }
        __syncthreads();
    }

    // Epilogue
#pragma unroll
    for (int mt = 0; mt < 2; mt++) {
        const int r0 = m0 + wm * 32 + mt * 16 + g;
#pragma unroll
        for (int nt = 0; nt < 8; nt++) {
            const int col = n0 + wn * 64 + nt * 8 + 2 * c;
            const float bb0 = bias[col], bb1 = bias[col + 1];
            const float v00 = acc[mt][nt][0] + bb0;
            const float v01 = acc[mt][nt][1] + bb1;
            const float v10 = acc[mt][nt][2] + bb0;
            const float v11 = acc[mt][nt][3] + bb1;
            if (HEADS_OUT) {
                __half* out = (__half*)outv;
                const int hh = col >> 6, d = col & 63;
                const int b0i = r0 >> 11, s0 = r0 & 2047;
                const int r1 = r0 + 8;
                const int b1i = r1 >> 11, s1 = r1 & 2047;
                *(uint32_t*)&out[((long)(b0i * H_NUM + hh) * S_LEN + s0) * D_DIM + d] =
                    pack_h2(v00, v01);
                *(uint32_t*)&out[((long)(b1i * H_NUM + hh) * S_LEN + s1) * D_DIM + d] =
                    pack_h2(v10, v11);
            } else {
                float* out = (float*)outv;
                *(float2*)&out[(long)r0 * E_DIM + col] = make_float2(v00, v01);
                *(float2*)&out[(long)(r0 + 8) * E_DIM + col] = make_float2(v10, v11);
            }
        }
    }
}

// ---------------------------------------------------------------------------
// fp16 flash attention, cp.async double-buffered, ldmatrix.x4 frag loads.
// Block = 4 warps, Br=64, Bc=64, D=64, half in/out.
// ---------------------------------------------------------------------------
#define SCALE2 (0.125f * 1.44269504088896f)  // 1/sqrt(64) * log2(e)
#define KST 72
#define TILE_HALVES (64 * KST)   // 4608

__global__ __launch_bounds__(128) void attn_f16(const int* __restrict__ mask,
                                                const __half* __restrict__ Qh,
                                                const __half* __restrict__ Kh,
                                                const __half* __restrict__ Vh,
                                                __half* __restrict__ ctx) {
    __shared__ __half KVs[2][2][TILE_HALVES];  // [stage][K=0/V=1]
    __shared__ int maskS[2][64];

    const int b = blockIdx.z, h = blockIdx.y;
    const int q0 = blockIdx.x * 64;
    const int tid = threadIdx.x;
    const int lane = tid & 31, w = tid >> 5;
    const int g = lane >> 2, c = lane & 3;

    const long base = (long)(b * H_NUM + h) * S_LEN * D_DIM;
    const __half* Q = Qh + base;
    const __half* K = Kh + base;
    const __half* V = Vh + base;
    const int* mrow = mask + b * S_LEN;

    const uint32_t kv_sb = (uint32_t)__cvta_generic_to_shared(&KVs[0][0][0]);
    const uint32_t mk_sb = (uint32_t)__cvta_generic_to_shared(&maskS[0][0]);

    // ldmatrix per-lane address components
    const int krow_l = (lane & 7) + (lane >> 4) * 8;   // K: row within 16-pair
    const int kcol_l = ((lane >> 3) & 1) * 8;          // K: +8 halves for b1
    const int vrow_l = lane & 15;                      // V: row within k-group
    const int vsel_l = lane >> 4;                      // V: n-block select

    // Q A-fragments (pre-scaled, fp16)
    uint32_t aq[4][4];
    {
        const __half* q_r0 = Q + (long)(q0 + w * 16 + g) * D_DIM;
        const __half* q_r1 = q_r0 + 8 * D_DIM;
#pragma unroll
        for (int ks = 0; ks < 4; ks++) {
            float2 p0 = __half22float2(*(const __half2*)&q_r0[ks * 16 + 2 * c]);
            float2 p1 = __half22float2(*(const __half2*)&q_r1[ks * 16 + 2 * c]);
            float2 p2 = __half22float2(*(const __half2*)&q_r0[ks * 16 + 2 * c + 8]);
            float2 p3 = __half22float2(*(const __half2*)&q_r1[ks * 16 + 2 * c + 8]);
            aq[ks][0] = pack_h2(p0.x * SCALE2, p0.y * SCALE2);
            aq[ks][1] = pack_h2(p1.x * SCALE2, p1.y * SCALE2);
            aq[ks][2] = pack_h2(p2.x * SCALE2, p2.y * SCALE2);
            aq[ks][3] = pack_h2(p3.x * SCALE2, p3.y * SCALE2);
        }
    }

    float O[8][4];
#pragma unroll
    for (int nt = 0; nt < 8; nt++)
#pragma unroll
        for (int j = 0; j < 4; j++) O[nt][j] = 0.0f;
    float mm0 = -1e30f, mm1 = -1e30f, l0 = 0.0f, l1 = 0.0f;

    auto issue_tile = [&](int kt, int st) {
        const int k0 = kt * 64;
        const uint32_t kb = kv_sb + (uint32_t)((st * 2) * TILE_HALVES * 2);
        const uint32_t vb = kb + (uint32_t)(TILE_HALVES * 2);
#pragma unroll
        for (int i = 0; i < 4; i++) {
            const int ch = i * 128 + tid;
            const int r = ch >> 3, o = (ch & 7) * 8;
            cp16(kb + (uint32_t)(r * KST + o) * 2, K + (long)(k0 + r) * D_DIM + o);
            cp16(vb + (uint32_t)(r * KST + o) * 2, V + (long)(k0 + r) * D_DIM + o);
        }
        if (tid < 16)
            cp16(mk_sb + (uint32_t)(st * 256 + tid * 16), mrow + k0 + tid * 4);
    };

    issue_tile(0, 0);
    CP_COMMIT();

    const int NTILES = S_LEN / 64;  // 32
    for (int t = 0; t < NTILES; t++) {
        if (t + 1 < NTILES) {
            issue_tile(t + 1, (t + 1) & 1);
            CP_COMMIT();
            CP_WAIT1();
        } else {
            CP_WAIT0();
        }
        __syncthreads();

        const int st = t & 1;
        const uint32_t ks_addr = kv_sb + (uint32_t)((st * 2) * TILE_HALVES * 2);
        const uint32_t vs_addr = ks_addr + (uint32_t)(TILE_HALVES * 2);
        const int* mskp = &maskS[st][0];

        // S = (Q*scale) K^T  — K frags via ldmatrix.x4
        float S[8][4];
#pragma unroll
        for (int nt = 0; nt < 8; nt++)
#pragma unroll
            for (int j = 0; j < 4; j++) S[nt][j] = 0.0f;

#pragma unroll
        for (int ks = 0; ks < 4; ks++) {
#pragma unroll
            for (int ntp = 0; ntp < 4; ntp++) {
                uint32_t b0, b1, b2, b3;
                ldsm_x4(b0, b1, b2, b3,
                        ks_addr + (uint32_t)(((ntp * 16 + krow_l) * KST +
                                              ks * 16 + kcol_l) * 2));
                mma_f16(S[2 * ntp], aq[ks][0], aq[ks][1], aq[ks][2], aq[ks][3], b0, b1);
                mma_f16(S[2 * ntp + 1], aq[ks][0], aq[ks][1], aq[ks][2], aq[ks][3], b2, b3);
            }
        }

        // mask bias + online softmax
        float mx0 = -1e30f, mx1 = -1e30f;
#pragma unroll
        for (int nt = 0; nt < 8; nt++) {
            const float bb0 = mskp[nt * 8 + 2 * c] ? 0.0f : -1.442695e9f;
            const float bb1 = mskp[nt * 8 + 2 * c + 1] ? 0.0f : -1.442695e9f;
            S[nt][0] += bb0;
            S[nt][1] += bb1;
            S[nt][2] += bb0;
            S[nt][3] += bb1;
            mx0 = fmaxf(mx0, fmaxf(S[nt][0], S[nt][1]));
            mx1 = fmaxf(mx1, fmaxf(S[nt][2], S[nt][3]));
        }
        mx0 = fmaxf(mx0, __shfl_xor_sync(0xffffffffu, mx0, 1));
        mx0 = fmaxf(mx0, __shfl_xor_sync(0xffffffffu, mx0, 2));
        mx1 = fmaxf(mx1, __shfl_xor_sync(0xffffffffu, mx1, 1));
        mx1 = fmaxf(mx1, __shfl_xor_sync(0xffffffffu, mx1, 2));

        const float M0 = fmaxf(mm0, mx0), M1 = fmaxf(mm1, mx1);
        const float a0 = ex2(mm0 - M0), a1 = ex2(mm1 - M1);
        mm0 = M0;
        mm1 = M1;

        float s0 = 0.0f, s1 = 0.0f;
        uint32_t Pp[8][2];
#pragma unroll
        for (int nt = 0; nt < 8; nt++) {
            S[nt][0] = ex2(S[nt][0] - M0);
            S[nt][1] = ex2(S[nt][1] - M0);
            S[nt][2] = ex2(S[nt][2] - M1);
            S[nt][3] = ex2(S[nt][3] - M1);
            s0 += S[nt][0] + S[nt][1];
            s1 += S[nt][2] + S[nt][3];
            Pp[nt][0] = pack_h2(S[nt][0], S[nt][1]);
            Pp[nt][1] = pack_h2(S[nt][2], S[nt][3]);
        }
        s0 += __shfl_xor_sync(0xffffffffu, s0, 1);
        s0 += __shfl_xor_sync(0xffffffffu, s0, 2);
        s1 += __shfl_xor_sync(0xffffffffu, s1, 1);
        s1 += __shfl_xor_sync(0xffffffffu, s1, 2);
        l0 = l0 * a0 + s0;
        l1 = l1 * a1 + s1;

#pragma unroll
        for (int nt = 0; nt < 8; nt++) {
            O[nt][0] *= a0;
            O[nt][1] *= a0;
            O[nt][2] *= a1;
            O[nt][3] *= a1;
        }

        // O += P @ V ; V frags via ldmatrix.x4.trans
#pragma unroll
        for (int ks = 0; ks < 4; ks++) {
            const uint32_t rowa =
                vs_addr + (uint32_t)(((ks * 16 + vrow_l) * KST) * 2);
#pragma unroll
            for (int ntp = 0; ntp < 4; ntp++) {
                uint32_t b0, b1, b2, b3;
                ldsm_x4_t(b0, b1, b2, b3,
                          rowa + (uint32_t)((ntp * 2 + vsel_l) * 16));
                mma_f16(O[2 * ntp], Pp[2 * ks][0], Pp[2 * ks][1],
                        Pp[2 * ks + 1][0], Pp[2 * ks + 1][1], b0, b1);
                mma_f16(O[2 * ntp + 1], Pp[2 * ks][0], Pp[2 * ks][1],
                        Pp[2 * ks + 1][0], Pp[2 * ks + 1][1], b2, b3);
            }
        }
        __syncthreads();
    }

    // epilogue: ctx half
    const float inv0 = 1.0f / l0, inv1 = 1.0f / l1;
    const int r0 = q0 + w * 16 + g;
#pragma unroll
    for (int nt = 0; nt < 8; nt++) {
        const int col = h * D_DIM + nt * 8 + 2 * c;
        *(uint32_t*)&ctx[((long)b * S_LEN + r0) * E_DIM + col] =
            pack_h2(O[nt][0] * inv0, O[nt][1] * inv0);
        *(uint32_t*)&ctx[((long)b * S_LEN + r0 + 8) * E_DIM + col] =
            pack_h2(O[nt][2] * inv1, O[nt][3] * inv1);
    }
}

// ---------------------------------------------------------------------------
extern "C" void kernel_launch(void* const* d_in, const int* in_sizes, int n_in,
                              void* d_out, int out_size) {
    const float* q = (const float*)d_in[0];
    const float* k = (const float*)d_in[1];
    const float* v = (const float*)d_in[2];
    const int* mask = (const int*)d_in[3];
    const float* Wq = (const float*)d_in[4];
    const float* bq = (const float*)d_in[5];
    const float* Wk = (const float*)d_in[6];
    const float* bk = (const float*)d_in[7];
    const float* Wv = (const float*)d_in[8];
    const float* bv = (const float*)d_in[9];
    const float* Wo = (const float*)d_in[10];
    const float* bo = (const float*)d_in[11];

    __half *Xh, *Wt, *Qh, *Kh, *Vh, *Ctx;
    cudaGetSymbolAddress((void**)&Xh, g_Xh);
    cudaGetSymbolAddress((void**)&Wt, g_Wt);
    cudaGetSymbolAddress((void**)&Qh, g_Qh);
    cudaGetSymbolAddress((void**)&Kh, g_Kh);
    cudaGetSymbolAddress((void**)&Vh, g_Vh);
    cudaGetSymbolAddress((void**)&Ctx, g_ctx);

    cudaFuncSetAttribute(gemm_f16<true>,
                         cudaFuncAttributeMaxDynamicSharedMemorySize, GEMM_SMEM);
    cudaFuncSetAttribute(gemm_f16<false>,
                         cudaFuncAttributeMaxDynamicSharedMemorySize, GEMM_SMEM);

    // converts
    cvt_x<<<dim3(ME / 1024, 3), 256>>>(q, k, v);
    cvt_wt<<<dim3(24, 24, 4), dim3(32, 8)>>>(Wq, Wk, Wv, Wo);

    // merged Q/K/V projections
    gemm_f16<true><<<dim3(6, 64, 3), 256, GEMM_SMEM>>>(Xh, Wt, bq, bk, bv, Qh,
                                                       Kh, Vh);

    attn_f16<<<dim3(S_LEN / 64, H_NUM, B_NUM), 128>>>(mask, Qh, Kh, Vh, Ctx);

    gemm_f16<false><<<dim3(6, 64, 1), 256, GEMM_SMEM>>>(
        Ctx, Wt + 3ll * WE, bo, bo, bo, d_out, d_out, d_out);
}